// round 1
// baseline (speedup 1.0000x reference)
#include <cuda_runtime.h>
#include <math.h>

// Problem dims
#define BB 64
#define DD 1024
#define TT 128
#define SS 128
#define EE 512

// ---------------- device scratch (no allocations allowed) ----------------
__device__ float g_h0[2][BB][DD];
__device__ float g_h1[2][BB][DD];
__device__ float g_c0[BB][DD];
__device__ float g_c1[BB][DD];
__device__ float g_out[BB][DD];    // input-feed vector
__device__ float g_q[BB][DD];
__device__ float g_wctx[BB][DD];

__device__ __forceinline__ float sigm(float x) { return 1.f / (1.f + __expf(-x)); }

// ---------------- init: copy initial state into scratch ----------------
__global__ void init_kernel(const float* __restrict__ h0,
                            const float* __restrict__ c0,
                            const float* __restrict__ init_out) {
    int i = blockIdx.x * blockDim.x + threadIdx.x;
    if (i < BB * DD) {
        ((float*)g_h0[0])[i] = h0[i];
        ((float*)g_h1[0])[i] = h0[BB * DD + i];
        ((float*)g_c0)[i]    = c0[i];
        ((float*)g_c1)[i]    = c0[BB * DD + i];
        ((float*)g_out)[i]   = init_out[i];
    }
}

// ---------------- fused LSTM layer: gates GEMM + cell ----------------
// CTA: 8 hidden units x 4 gates (=32 weight rows) x all 64 batches.
// Grid: 128 CTAs (1024/8). blockDim 256. Per-thread 2x4 accumulator tile.
__global__ __launch_bounds__(256, 1) void lstm_kernel(
    int layer, int cur, int t,
    const float* __restrict__ Wih, const float* __restrict__ Whh,
    const float* __restrict__ bih, const float* __restrict__ bhh,
    const float* __restrict__ word_lut, const int* __restrict__ input) {
    __shared__ float xs[64][33];
    __shared__ float ws[32][33];
    __shared__ float sg[32][65];
    __shared__ int toks[64];

    const int tid = threadIdx.x;
    const int u0 = blockIdx.x * 8;
    const int K1 = (layer == 0) ? (EE + DD) : DD;  // x width: 1536 / 1024
    const int Ktot = K1 + DD;

    if (layer == 0 && tid < 64) toks[tid] = input[tid * TT + t];

    const float (*hprev)[DD] = layer ? g_h1[cur] : g_h0[cur];
    float (*hnew)[DD]        = layer ? g_h1[cur ^ 1] : g_h0[cur ^ 1];
    float (*cst)[DD]         = layer ? g_c1 : g_c0;
    const float (*h0n)[DD]   = g_h0[cur ^ 1];  // layer1 input = new h0

    __syncthreads();

    const int r  = tid & 15;   // row-pair index: rows 2r, 2r+1
    const int cb = tid >> 4;   // batch group of 4
    float acc[2][4] = {};

    for (int k0 = 0; k0 < Ktot; k0 += 32) {
        // stage x chunk [64 x 32]
        #pragma unroll
        for (int i = 0; i < 8; i++) {
            int e = tid + i * 256;
            int b = e >> 5, kk = e & 31;
            int k = k0 + kk;
            float v;
            if (layer == 0) {
                if (k < EE)            v = word_lut[toks[b] * EE + k];
                else if (k < EE + DD)  v = g_out[b][k - EE];
                else                   v = hprev[b][k - (EE + DD)];
            } else {
                if (k < DD) v = h0n[b][k];
                else        v = hprev[b][k - DD];
            }
            xs[b][kk] = v;
        }
        // stage weight chunk [32 rows x 32]
        #pragma unroll
        for (int i = 0; i < 4; i++) {
            int e = tid + i * 256;
            int lr = e >> 5, kk = e & 31;
            int gate = lr >> 3, u = lr & 7;
            int grow = gate * DD + u0 + u;
            int k = k0 + kk;
            ws[lr][kk] = (k < K1) ? Wih[grow * K1 + k] : Whh[grow * DD + (k - K1)];
        }
        __syncthreads();
        #pragma unroll
        for (int kk = 0; kk < 32; kk++) {
            float w0 = ws[2 * r][kk], w1 = ws[2 * r + 1][kk];
            float x0 = xs[cb * 4 + 0][kk];
            float x1 = xs[cb * 4 + 1][kk];
            float x2 = xs[cb * 4 + 2][kk];
            float x3 = xs[cb * 4 + 3][kk];
            acc[0][0] += w0 * x0; acc[0][1] += w0 * x1; acc[0][2] += w0 * x2; acc[0][3] += w0 * x3;
            acc[1][0] += w1 * x0; acc[1][1] += w1 * x1; acc[1][2] += w1 * x2; acc[1][3] += w1 * x3;
        }
        __syncthreads();
    }

    // combine gates across threads via shared, then apply the cell
    #pragma unroll
    for (int i = 0; i < 4; i++) {
        sg[2 * r][cb * 4 + i]     = acc[0][i];
        sg[2 * r + 1][cb * 4 + i] = acc[1][i];
    }
    __syncthreads();
    #pragma unroll
    for (int i = 0; i < 2; i++) {
        int idx = tid + i * 256;
        int u = idx >> 6, b = idx & 63;
        int d = u0 + u;
        float iv = sg[u][b]      + bih[d]          + bhh[d];
        float fv = sg[8 + u][b]  + bih[DD + d]     + bhh[DD + d];
        float gv = sg[16 + u][b] + bih[2 * DD + d] + bhh[2 * DD + d];
        float ov = sg[24 + u][b] + bih[3 * DD + d] + bhh[3 * DD + d];
        float cp = cst[b][d];
        float cn = sigm(fv) * cp + sigm(iv) * tanhf(gv);
        float hn = sigm(ov) * tanhf(cn);
        cst[b][d]  = cn;
        hnew[b][d] = hn;
    }
}

// ---------------- small GEMM: q = h1 @ W_in^T  or  out = tanh([wctx,h1] @ W_out^T)
// CTA: 16 output dims x 64 batches. Grid 64. blockDim 128. Per-thread 2x4 tile.
__global__ __launch_bounds__(128, 1) void gemm_kernel(
    int mode, int hbuf, int t,
    const float* __restrict__ W, float* __restrict__ outs) {
    __shared__ float xs[64][33];
    __shared__ float ws[16][33];
    const int tid = threadIdx.x;
    const int d0 = blockIdx.x * 16;
    const int K = (mode == 0) ? DD : 2 * DD;
    const float (*h1)[DD] = g_h1[hbuf];

    const int r  = tid & 7;
    const int cb = tid >> 3;
    float acc[2][4] = {};

    for (int k0 = 0; k0 < K; k0 += 32) {
        #pragma unroll
        for (int i = 0; i < 16; i++) {
            int e = tid + i * 128;
            int b = e >> 5, kk = e & 31;
            int k = k0 + kk;
            float v;
            if (mode == 0) v = h1[b][k];
            else           v = (k < DD) ? g_wctx[b][k] : h1[b][k - DD];
            xs[b][kk] = v;
        }
        #pragma unroll
        for (int i = 0; i < 4; i++) {
            int e = tid + i * 128;
            int lr = e >> 5, kk = e & 31;
            ws[lr][kk] = W[(size_t)(d0 + lr) * K + k0 + kk];
        }
        __syncthreads();
        #pragma unroll
        for (int kk = 0; kk < 32; kk++) {
            float w0 = ws[2 * r][kk], w1 = ws[2 * r + 1][kk];
            float x0 = xs[cb * 4 + 0][kk];
            float x1 = xs[cb * 4 + 1][kk];
            float x2 = xs[cb * 4 + 2][kk];
            float x3 = xs[cb * 4 + 3][kk];
            acc[0][0] += w0 * x0; acc[0][1] += w0 * x1; acc[0][2] += w0 * x2; acc[0][3] += w0 * x3;
            acc[1][0] += w1 * x0; acc[1][1] += w1 * x1; acc[1][2] += w1 * x2; acc[1][3] += w1 * x3;
        }
        __syncthreads();
    }

    #pragma unroll
    for (int j = 0; j < 2; j++)
        #pragma unroll
        for (int i = 0; i < 4; i++) {
            int d = d0 + 2 * r + j;
            int b = cb * 4 + i;
            float v = acc[j][i];
            if (mode == 0) {
                g_q[b][d] = v;
            } else {
                v = tanhf(v);
                g_out[b][d] = v;
                outs[((size_t)b * TT + t) * DD + d] = v;
            }
        }
}

// ---------------- attention: scores + softmax + weighted context ----------------
// Grid 64 (one CTA per batch). blockDim 128.
__global__ __launch_bounds__(128, 1) void attn_kernel(
    int t, const float* __restrict__ context, float* __restrict__ attns) {
    __shared__ float qs[DD];
    __shared__ float sc[SS];
    __shared__ float red[4];
    const int b = blockIdx.x;
    const int tid = threadIdx.x;
    const int lane = tid & 31, warp = tid >> 5;

    for (int i = tid; i < DD; i += 128) qs[i] = g_q[b][i];
    __syncthreads();

    // scores[s] = ctx[b,s,:] . q   (ctx layout [S,B,D])
    for (int s = warp; s < SS; s += 4) {
        const float4* cp = (const float4*)(context + (size_t)(s * BB + b) * DD);
        float p = 0.f;
        #pragma unroll
        for (int i = 0; i < 8; i++) {
            int d4 = lane + i * 32;
            float4 v = cp[d4];
            p += v.x * qs[d4 * 4] + v.y * qs[d4 * 4 + 1] + v.z * qs[d4 * 4 + 2] + v.w * qs[d4 * 4 + 3];
        }
        #pragma unroll
        for (int off = 16; off; off >>= 1) p += __shfl_xor_sync(0xffffffffu, p, off);
        if (lane == 0) sc[s] = p;
    }
    __syncthreads();

    // softmax over S=128 (each thread owns one s)
    float v = sc[tid];
    float m = v;
    #pragma unroll
    for (int off = 16; off; off >>= 1) m = fmaxf(m, __shfl_xor_sync(0xffffffffu, m, off));
    if (lane == 0) red[warp] = m;
    __syncthreads();
    m = fmaxf(fmaxf(red[0], red[1]), fmaxf(red[2], red[3]));
    float e = __expf(v - m);
    float ssum = e;
    #pragma unroll
    for (int off = 16; off; off >>= 1) ssum += __shfl_xor_sync(0xffffffffu, ssum, off);
    __syncthreads();
    if (lane == 0) red[warp] = ssum;
    __syncthreads();
    ssum = red[0] + red[1] + red[2] + red[3];
    float a = e / ssum;
    sc[tid] = a;
    attns[((size_t)b * TT + t) * SS + tid] = a;
    __syncthreads();

    // wctx[d] = sum_s a[s] * ctx[b,s,d]
    float4 acc0 = {0, 0, 0, 0}, acc1 = {0, 0, 0, 0};
    const int dA = tid * 4, dB = tid * 4 + 512;
    for (int s = 0; s < SS; s++) {
        float as = sc[s];
        const float4* cp = (const float4*)(context + (size_t)(s * BB + b) * DD);
        float4 vA = cp[dA >> 2];
        float4 vB = cp[dB >> 2];
        acc0.x += as * vA.x; acc0.y += as * vA.y; acc0.z += as * vA.z; acc0.w += as * vA.w;
        acc1.x += as * vB.x; acc1.y += as * vB.y; acc1.z += as * vB.z; acc1.w += as * vB.w;
    }
    *(float4*)&g_wctx[b][dA] = acc0;
    *(float4*)&g_wctx[b][dB] = acc1;
}

// ---------------- final: emit h, c ----------------
__global__ void final_kernel(float* __restrict__ hout, float* __restrict__ cout) {
    int i = blockIdx.x * blockDim.x + threadIdx.x;
    if (i < BB * DD) {
        hout[i]           = ((float*)g_h0[0])[i];   // after T=128 steps, state lives in buf 0
        hout[BB * DD + i] = ((float*)g_h1[0])[i];
        cout[i]           = ((float*)g_c0)[i];
        cout[BB * DD + i] = ((float*)g_c1)[i];
    }
}

// ---------------- launch ----------------
extern "C" void kernel_launch(void* const* d_in, const int* in_sizes, int n_in,
                              void* d_out, int out_size) {
    const int*   input    = (const int*)d_in[0];
    // d_in[1] = input_rb: unused by the reference
    const float* h0       = (const float*)d_in[2];
    const float* c0       = (const float*)d_in[3];
    const float* context  = (const float*)d_in[4];
    const float* init_out = (const float*)d_in[5];
    const float* word_lut = (const float*)d_in[6];
    const float* Wih0 = (const float*)d_in[7];
    const float* Whh0 = (const float*)d_in[8];
    const float* bih0 = (const float*)d_in[9];
    const float* bhh0 = (const float*)d_in[10];
    const float* Wih1 = (const float*)d_in[11];
    const float* Whh1 = (const float*)d_in[12];
    const float* bih1 = (const float*)d_in[13];
    const float* bhh1 = (const float*)d_in[14];
    const float* Win  = (const float*)d_in[15];
    const float* Wout = (const float*)d_in[16];

    float* out   = (float*)d_out;
    float* outs  = out;                                // [B,T,D]
    float* hout  = out + (size_t)BB * TT * DD;         // [2,B,D]
    float* cout  = hout + 2 * BB * DD;                 // [2,B,D]
    float* attns = cout + 2 * BB * DD;                 // [B,T,S]

    init_kernel<<<(BB * DD + 255) / 256, 256>>>(h0, c0, init_out);
    for (int t = 0; t < TT; t++) {
        int cur = t & 1;
        lstm_kernel<<<128, 256>>>(0, cur, t, Wih0, Whh0, bih0, bhh0, word_lut, input);
        lstm_kernel<<<128, 256>>>(1, cur, t, Wih1, Whh1, bih1, bhh1, word_lut, input);
        gemm_kernel<<<64, 128>>>(0, cur ^ 1, t, Win, outs);
        attn_kernel<<<64, 128>>>(t, context, attns);
        gemm_kernel<<<64, 128>>>(1, cur ^ 1, t, Wout, outs);
    }
    final_kernel<<<(BB * DD + 255) / 256, 256>>>(hout, cout);
}

// round 4
// speedup vs baseline: 2.5400x; 2.5400x over previous
#include <cuda_runtime.h>
#include <math.h>

#define BB 64
#define DD 1024
#define TT 128
#define SS 128
#define EE 512
#define NCTA 128

typedef unsigned long long ull;

// ---------------- device scratch (static, no allocations) ----------------
__device__ float g_h0[BB][DD];
__device__ float g_h1[BB][DD];
__device__ float g_c0[BB][DD];
__device__ float g_c1[BB][DD];
__device__ float g_out[BB][DD];
__device__ float g_wctx[BB][DD];
__device__ float g_bias0[4 * DD];
__device__ float g_bias1[4 * DD];
__device__ float g_WinT[DD * DD];                 // W_in transposed: [k][d]
__device__ float g_Cq[(size_t)SS * BB * DD];      // ctx @ W_in  : [s][b][k]
__device__ float g_part[4 * 4096 * 64];           // split-K partials (4MB)

__device__ unsigned g_bar_count;
__device__ volatile unsigned g_bar_epoch;

__device__ __forceinline__ float sigm(float x) { return 1.f / (1.f + __expf(-x)); }

__device__ __forceinline__ void ffma2(ull &d, ull a, ull b) {
    asm("fma.rn.f32x2 %0, %1, %2, %0;" : "+l"(d) : "l"(a), "l"(b));
}
__device__ __forceinline__ ull dup2(float w) {
    ull r; asm("mov.b64 %0, {%1, %1};" : "=l"(r) : "f"(w)); return r;
}

// software grid barrier (all NCTA CTAs resident: 128 <= 148 SMs @ 1 CTA/SM)
__device__ __forceinline__ void grid_barrier() {
    __syncthreads();
    if (threadIdx.x == 0) {
        unsigned e = g_bar_epoch;
        __threadfence();
        unsigned a = atomicAdd(&g_bar_count, 1u);
        if (a == NCTA - 1) {
            g_bar_count = 0;
            __threadfence();
            atomicAdd((unsigned*)&g_bar_epoch, 1u);
        } else {
            while (g_bar_epoch == e) { __nanosleep(32); }
        }
        __threadfence();
    }
    __syncthreads();
}

// ---------------- init ----------------
__global__ void init_kernel(const float* __restrict__ h0, const float* __restrict__ c0,
                            const float* __restrict__ io,
                            const float* __restrict__ bih0, const float* __restrict__ bhh0,
                            const float* __restrict__ bih1, const float* __restrict__ bhh1) {
    int i = blockIdx.x * blockDim.x + threadIdx.x;
    if (i < BB * DD) {
        ((float*)g_h0)[i] = h0[i];
        ((float*)g_h1)[i] = h0[BB * DD + i];
        ((float*)g_c0)[i] = c0[i];
        ((float*)g_c1)[i] = c0[BB * DD + i];
        ((float*)g_out)[i] = io[i];
    }
    if (i < 4 * DD) {
        g_bias0[i] = bih0[i] + bhh0[i];
        g_bias1[i] = bih1[i] + bhh1[i];
    }
}

// ---------------- transpose W_in ----------------
__global__ void transpose_kernel(const float* __restrict__ Win) {
    __shared__ float tile[32][33];
    int bx = blockIdx.x * 32, by = blockIdx.y * 32;
    int x = threadIdx.x, y0 = threadIdx.y;  // blockDim (32,8)
    #pragma unroll
    for (int j = 0; j < 32; j += 8)
        tile[y0 + j][x] = Win[(size_t)(by + y0 + j) * DD + bx + x];
    __syncthreads();
    #pragma unroll
    for (int j = 0; j < 32; j += 8)
        g_WinT[(size_t)(bx + y0 + j) * DD + by + x] = tile[x][y0 + j];
}

// ---------------- Cq precompute: Cq[s][b][k] = sum_d context[s][b][d] * WinT[k][d]
// grid (8 k-rowtiles, 128 s), 256 threads, tile 128 k x 64 b, full K=1024.
__global__ __launch_bounds__(256, 1) void cq_kernel(const float* __restrict__ context) {
    __shared__ float ws[32][128];
    __shared__ float xs[32][64];
    const int tid = threadIdx.x;
    const int rowBase = blockIdx.x * 128;
    const int s = blockIdx.y;
    const int rg4 = (tid >> 3) << 2, b8 = (tid & 7) << 3;
    const int wrow = tid & 127, wkh = tid >> 7;
    const int xb = tid & 63, xkg = tid >> 6;

    ull acc[4][4];
    #pragma unroll
    for (int r = 0; r < 4; r++)
        #pragma unroll
        for (int p = 0; p < 4; p++) acc[r][p] = 0ull;

    for (int k0 = 0; k0 < DD; k0 += 32) {
        {
            const float* src = g_WinT + (size_t)(rowBase + wrow) * DD + k0 + wkh * 16;
            #pragma unroll
            for (int i = 0; i < 16; i += 4) {
                float4 v = *(const float4*)(src + i);
                ws[wkh * 16 + i + 0][wrow] = v.x;
                ws[wkh * 16 + i + 1][wrow] = v.y;
                ws[wkh * 16 + i + 2][wrow] = v.z;
                ws[wkh * 16 + i + 3][wrow] = v.w;
            }
        }
        {
            const float* src = context + (size_t)(s * BB + xb) * DD + k0 + xkg * 8;
            float4 v0 = *(const float4*)(src);
            float4 v1 = *(const float4*)(src + 4);
            xs[xkg * 8 + 0][xb] = v0.x; xs[xkg * 8 + 1][xb] = v0.y;
            xs[xkg * 8 + 2][xb] = v0.z; xs[xkg * 8 + 3][xb] = v0.w;
            xs[xkg * 8 + 4][xb] = v1.x; xs[xkg * 8 + 5][xb] = v1.y;
            xs[xkg * 8 + 6][xb] = v1.z; xs[xkg * 8 + 7][xb] = v1.w;
        }
        __syncthreads();
        #pragma unroll 8
        for (int kk = 0; kk < 32; kk++) {
            float4 wv = *(const float4*)&ws[kk][rg4];
            ull w0 = dup2(wv.x), w1 = dup2(wv.y), w2 = dup2(wv.z), w3 = dup2(wv.w);
            ulonglong2 xa = *(const ulonglong2*)&xs[kk][b8];
            ulonglong2 xc = *(const ulonglong2*)&xs[kk][b8 + 4];
            ffma2(acc[0][0], w0, xa.x); ffma2(acc[0][1], w0, xa.y);
            ffma2(acc[0][2], w0, xc.x); ffma2(acc[0][3], w0, xc.y);
            ffma2(acc[1][0], w1, xa.x); ffma2(acc[1][1], w1, xa.y);
            ffma2(acc[1][2], w1, xc.x); ffma2(acc[1][3], w1, xc.y);
            ffma2(acc[2][0], w2, xa.x); ffma2(acc[2][1], w2, xa.y);
            ffma2(acc[2][2], w2, xc.x); ffma2(acc[2][3], w2, xc.y);
            ffma2(acc[3][0], w3, xa.x); ffma2(acc[3][1], w3, xa.y);
            ffma2(acc[3][2], w3, xc.x); ffma2(acc[3][3], w3, xc.y);
        }
        __syncthreads();
    }
    #pragma unroll
    for (int r = 0; r < 4; r++) {
        int krow = rowBase + rg4 + r;
        #pragma unroll
        for (int p = 0; p < 4; p++) {
            float2 v = *(float2*)&acc[r][p];
            g_Cq[(size_t)(s * BB + b8 + 2 * p) * DD + krow]     = v.x;
            g_Cq[(size_t)(s * BB + b8 + 2 * p + 1) * DD + krow] = v.y;
        }
    }
}

// ---------------- fused-step phases ----------------
// gemm tile: 128 rows x 64 batches, split-K; partials to g_part.
// modes: 0 = lstm0 x=[emb|out|h0], 1 = lstm1 x=[h0|h1], 3 = out x=[wctx|h1]
__device__ __forceinline__ void gemm_tile(
    int mode, int rowBase, int ksBase, int KS, int K1w,
    const float* __restrict__ W1, const float* __restrict__ W2,
    float* __restrict__ partOut,
    const float* __restrict__ word_lut, const int* toks,
    float (*ws)[128], float (*xs)[64]) {
    const int tid = threadIdx.x;
    const int rg4 = (tid >> 3) << 2, b8 = (tid & 7) << 3;
    const int wrow = tid & 127, wkh = tid >> 7;
    const int xb = tid & 63, xkg = tid >> 6;

    ull acc[4][4];
    #pragma unroll
    for (int r = 0; r < 4; r++)
        #pragma unroll
        for (int p = 0; p < 4; p++) acc[r][p] = 0ull;

    for (int k0 = ksBase; k0 < ksBase + KS; k0 += 32) {
        {
            int kb = k0 + wkh * 16;
            const float* src = (kb < K1w)
                ? W1 + (size_t)(rowBase + wrow) * K1w + kb
                : W2 + (size_t)(rowBase + wrow) * DD + (kb - K1w);
            #pragma unroll
            for (int i = 0; i < 16; i += 4) {
                float4 v = *(const float4*)(src + i);
                ws[wkh * 16 + i + 0][wrow] = v.x;
                ws[wkh * 16 + i + 1][wrow] = v.y;
                ws[wkh * 16 + i + 2][wrow] = v.z;
                ws[wkh * 16 + i + 3][wrow] = v.w;
            }
        }
        {
            int kb = k0 + xkg * 8;
            const float* src;
            if (mode == 0) {
                if (kb < EE)           src = word_lut + (size_t)toks[xb] * EE + kb;
                else if (kb < EE + DD) src = &g_out[xb][kb - EE];
                else                   src = &g_h0[xb][kb - (EE + DD)];
            } else if (mode == 1) {
                src = (kb < DD) ? &g_h0[xb][kb] : &g_h1[xb][kb - DD];
            } else {
                src = (kb < DD) ? &g_wctx[xb][kb] : &g_h1[xb][kb - DD];
            }
            float4 v0 = *(const float4*)(src);
            float4 v1 = *(const float4*)(src + 4);
            xs[xkg * 8 + 0][xb] = v0.x; xs[xkg * 8 + 1][xb] = v0.y;
            xs[xkg * 8 + 2][xb] = v0.z; xs[xkg * 8 + 3][xb] = v0.w;
            xs[xkg * 8 + 4][xb] = v1.x; xs[xkg * 8 + 5][xb] = v1.y;
            xs[xkg * 8 + 6][xb] = v1.z; xs[xkg * 8 + 7][xb] = v1.w;
        }
        __syncthreads();
        #pragma unroll 8
        for (int kk = 0; kk < 32; kk++) {
            float4 wv = *(const float4*)&ws[kk][rg4];
            ull w0 = dup2(wv.x), w1 = dup2(wv.y), w2 = dup2(wv.z), w3 = dup2(wv.w);
            ulonglong2 xa = *(const ulonglong2*)&xs[kk][b8];
            ulonglong2 xc = *(const ulonglong2*)&xs[kk][b8 + 4];
            ffma2(acc[0][0], w0, xa.x); ffma2(acc[0][1], w0, xa.y);
            ffma2(acc[0][2], w0, xc.x); ffma2(acc[0][3], w0, xc.y);
            ffma2(acc[1][0], w1, xa.x); ffma2(acc[1][1], w1, xa.y);
            ffma2(acc[1][2], w1, xc.x); ffma2(acc[1][3], w1, xc.y);
            ffma2(acc[2][0], w2, xa.x); ffma2(acc[2][1], w2, xa.y);
            ffma2(acc[2][2], w2, xc.x); ffma2(acc[2][3], w2, xc.y);
            ffma2(acc[3][0], w3, xa.x); ffma2(acc[3][1], w3, xa.y);
            ffma2(acc[3][2], w3, xc.x); ffma2(acc[3][3], w3, xc.y);
        }
        __syncthreads();
    }
    #pragma unroll
    for (int r = 0; r < 4; r++) {
        float* p = partOut + (size_t)(rowBase + rg4 + r) * 64 + b8;
        *(ulonglong2*)(p)     = make_ulonglong2(acc[r][0], acc[r][1]);
        *(ulonglong2*)(p + 4) = make_ulonglong2(acc[r][2], acc[r][3]);
    }
}

__device__ __forceinline__ void cell_phase(int layer) {
    int gid = blockIdx.x * 256 + threadIdx.x;
    const float* bias = layer ? g_bias1 : g_bias0;
    #pragma unroll
    for (int e = gid; e < BB * DD; e += NCTA * 256) {
        int b = e & 63, d = e >> 6;
        float g[4];
        #pragma unroll
        for (int gate = 0; gate < 4; gate++) {
            int row = gate * DD + d;
            float s = bias[row];
            #pragma unroll
            for (int ks = 0; ks < 4; ks++)
                s += g_part[((size_t)ks * 4096 + row) * 64 + b];
            g[gate] = s;
        }
        if (layer) {
            float cn = sigm(g[1]) * g_c1[b][d] + sigm(g[0]) * tanhf(g[2]);
            g_c1[b][d] = cn;
            g_h1[b][d] = sigm(g[3]) * tanhf(cn);
        } else {
            float cn = sigm(g[1]) * g_c0[b][d] + sigm(g[0]) * tanhf(g[2]);
            g_c0[b][d] = cn;
            g_h0[b][d] = sigm(g[3]) * tanhf(cn);
        }
    }
}

__device__ __forceinline__ void attn_phase(
    int t, int b, const float* __restrict__ context, float* __restrict__ attns,
    float* h1s, float* sc, float* red) {
    const int tid = threadIdx.x;
    const int lane = tid & 31, warp = tid >> 5;
    for (int i = tid; i < DD; i += 256) h1s[i] = g_h1[b][i];
    __syncthreads();

    // scores[s] = Cq[s,b,:] . h1[b,:]
    for (int s = warp; s < SS; s += 8) {
        const float4* cp = (const float4*)(g_Cq + (size_t)(s * BB + b) * DD);
        float p = 0.f;
        #pragma unroll
        for (int i = 0; i < 8; i++) {
            int d4 = lane + i * 32;
            float4 v = cp[d4];
            p += v.x * h1s[4 * d4] + v.y * h1s[4 * d4 + 1] +
                 v.z * h1s[4 * d4 + 2] + v.w * h1s[4 * d4 + 3];
        }
        #pragma unroll
        for (int off = 16; off; off >>= 1) p += __shfl_xor_sync(~0u, p, off);
        if (lane == 0) sc[s] = p;
    }
    __syncthreads();

    float v = (tid < 128) ? sc[tid] : -1e30f;
    float m = v;
    #pragma unroll
    for (int off = 16; off; off >>= 1) m = fmaxf(m, __shfl_xor_sync(~0u, m, off));
    if (tid < 128 && lane == 0) red[warp] = m;
    __syncthreads();
    m = fmaxf(fmaxf(red[0], red[1]), fmaxf(red[2], red[3]));
    float ex = (tid < 128) ? __expf(v - m) : 0.f;
    float ssum = ex;
    #pragma unroll
    for (int off = 16; off; off >>= 1) ssum += __shfl_xor_sync(~0u, ssum, off);
    __syncthreads();
    if (tid < 128 && lane == 0) red[warp] = ssum;
    __syncthreads();
    ssum = red[0] + red[1] + red[2] + red[3];
    if (tid < 128) {
        float a = ex / ssum;
        sc[tid] = a;
        attns[((size_t)b * TT + t) * SS + tid] = a;
    }
    __syncthreads();

    // wctx[d] = sum_s a[s] * ctx[s,b,d]
    float4 a4 = make_float4(0.f, 0.f, 0.f, 0.f);
    const int d4 = tid * 4;
    #pragma unroll 4
    for (int s = 0; s < SS; s++) {
        float as = sc[s];
        float4 vv = *(const float4*)(context + (size_t)(s * BB + b) * DD + d4);
        a4.x += as * vv.x; a4.y += as * vv.y; a4.z += as * vv.z; a4.w += as * vv.w;
    }
    *(float4*)&g_wctx[b][d4] = a4;
}

__device__ __forceinline__ void outred_phase(int t, float* __restrict__ outs) {
    int gid = blockIdx.x * 256 + threadIdx.x;
    #pragma unroll
    for (int e = gid; e < BB * DD; e += NCTA * 256) {
        int b = e & 63, d = e >> 6;
        float s = 0.f;
        #pragma unroll
        for (int ks = 0; ks < 16; ks++)
            s += g_part[((size_t)ks * 1024 + d) * 64 + b];
        float v = tanhf(s);
        g_out[b][d] = v;
        outs[((size_t)b * TT + t) * DD + d] = v;
    }
}

// ---------------- one timestep = one kernel ----------------
__global__ __launch_bounds__(256, 1) void step_kernel(
    int t, const int* __restrict__ input,
    const float* __restrict__ word_lut,
    const float* __restrict__ Wih0, const float* __restrict__ Whh0,
    const float* __restrict__ Wih1, const float* __restrict__ Whh1,
    const float* __restrict__ Wout,
    const float* __restrict__ context,
    float* __restrict__ outs, float* __restrict__ attns) {
    __shared__ float ws[32][128];
    __shared__ float xs[32][64];
    __shared__ int toks[64];
    __shared__ float sc[SS];
    __shared__ float red[4];

    const int tid = threadIdx.x;
    const int bid = blockIdx.x;
    if (tid < 64) toks[tid] = input[tid * TT + t];
    __syncthreads();

    // lstm0 gates: 4096 rows, K=2560, 32 rowtiles x 4 ksplit(640)
    gemm_tile(0, (bid & 31) * 128, (bid >> 5) * 640, 640, EE + DD,
              Wih0, Whh0, g_part + (size_t)(bid >> 5) * 4096 * 64,
              word_lut, toks, ws, xs);
    grid_barrier();
    cell_phase(0);
    grid_barrier();
    // lstm1 gates: 4096 rows, K=2048, 32 rowtiles x 4 ksplit(512)
    gemm_tile(1, (bid & 31) * 128, (bid >> 5) * 512, 512, DD,
              Wih1, Whh1, g_part + (size_t)(bid >> 5) * 4096 * 64,
              word_lut, toks, ws, xs);
    grid_barrier();
    cell_phase(1);
    grid_barrier();
    if (bid < 64) attn_phase(t, bid, context, attns, (float*)ws, sc, red);
    grid_barrier();
    // out gemm: 1024 rows, K=2048, 8 rowtiles x 16 ksplit(128)
    gemm_tile(3, (bid & 7) * 128, (bid >> 3) * 128, 128, 2 * DD,
              Wout, Wout, g_part + (size_t)(bid >> 3) * 1024 * 64,
              word_lut, toks, ws, xs);
    grid_barrier();
    outred_phase(t, outs);
}

// ---------------- final ----------------
__global__ void final_kernel(float* __restrict__ hout, float* __restrict__ cout) {
    int i = blockIdx.x * blockDim.x + threadIdx.x;
    if (i < BB * DD) {
        hout[i]           = ((float*)g_h0)[i];
        hout[BB * DD + i] = ((float*)g_h1)[i];
        cout[i]           = ((float*)g_c0)[i];
        cout[BB * DD + i] = ((float*)g_c1)[i];
    }
}

// ---------------- launch ----------------
extern "C" void kernel_launch(void* const* d_in, const int* in_sizes, int n_in,
                              void* d_out, int out_size) {
    const int*   input    = (const int*)d_in[0];
    const float* h0       = (const float*)d_in[2];
    const float* c0       = (const float*)d_in[3];
    const float* context  = (const float*)d_in[4];
    const float* init_out = (const float*)d_in[5];
    const float* word_lut = (const float*)d_in[6];
    const float* Wih0 = (const float*)d_in[7];
    const float* Whh0 = (const float*)d_in[8];
    const float* bih0 = (const float*)d_in[9];
    const float* bhh0 = (const float*)d_in[10];
    const float* Wih1 = (const float*)d_in[11];
    const float* Whh1 = (const float*)d_in[12];
    const float* bih1 = (const float*)d_in[13];
    const float* bhh1 = (const float*)d_in[14];
    const float* Win  = (const float*)d_in[15];
    const float* Wout = (const float*)d_in[16];

    float* out   = (float*)d_out;
    float* outs  = out;                           // [B,T,D]
    float* hout  = out + (size_t)BB * TT * DD;    // [2,B,D]
    float* cout  = hout + 2 * BB * DD;            // [2,B,D]
    float* attns = cout + 2 * BB * DD;            // [B,T,S]

    init_kernel<<<256, 256>>>(h0, c0, init_out, bih0, bhh0, bih1, bhh1);
    transpose_kernel<<<dim3(32, 32), dim3(32, 8)>>>(Win);
    cq_kernel<<<dim3(8, 128), 256>>>(context);
    for (int t = 0; t < TT; t++) {
        step_kernel<<<NCTA, 256>>>(t, input, word_lut, Wih0, Whh0, Wih1, Whh1,
                                   Wout, context, outs, attns);
    }
    final_kernel<<<256, 256>>>(hout, cout);
}

// round 5
// speedup vs baseline: 3.0634x; 1.2060x over previous
#include <cuda_runtime.h>
#include <math.h>

#define BB 64
#define DD 1024
#define TT 128
#define SS 128
#define EE 512
#define NCTA 128
#define NTHR 512

typedef unsigned long long ull;

// ---------------- device scratch (static, no allocations) ----------------
__device__ float g_h0[BB][DD];
__device__ float g_h1[BB][DD];
__device__ float g_c0[BB][DD];
__device__ float g_c1[BB][DD];
__device__ float g_out[BB][DD];
__device__ float g_wctx[BB][DD];
__device__ float g_bias0[4 * DD];
__device__ float g_bias1[4 * DD];
__device__ float g_WinT[DD * DD];                 // W_in transposed
__device__ float g_Cq[(size_t)SS * BB * DD];      // ctx @ W_in : [s][b][k]
__device__ float g_part[8 * 4096 * 64];           // split-K partials (8MB)

__device__ unsigned g_bar_count;
__device__ volatile unsigned g_bar_epoch;

__device__ __forceinline__ float sigm(float x) { return 1.f / (1.f + __expf(-x)); }

__device__ __forceinline__ void ffma2(ull &d, ull a, ull b) {
    asm("fma.rn.f32x2 %0, %1, %2, %0;" : "+l"(d) : "l"(a), "l"(b));
}
__device__ __forceinline__ ull dup2(float w) {
    ull r; asm("mov.b64 %0, {%1, %1};" : "=l"(r) : "f"(w)); return r;
}

// software grid barrier (128 CTAs, all resident)
__device__ __forceinline__ void grid_barrier() {
    __syncthreads();
    if (threadIdx.x == 0) {
        unsigned e = g_bar_epoch;
        __threadfence();
        unsigned a = atomicAdd(&g_bar_count, 1u);
        if (a == NCTA - 1) {
            g_bar_count = 0;
            __threadfence();
            atomicAdd((unsigned*)&g_bar_epoch, 1u);
        } else {
            while (g_bar_epoch == e) { __nanosleep(32); }
        }
        __threadfence();
    }
    __syncthreads();
}

// ---------------- init ----------------
__global__ void init_kernel(const float* __restrict__ h0, const float* __restrict__ c0,
                            const float* __restrict__ io,
                            const float* __restrict__ bih0, const float* __restrict__ bhh0,
                            const float* __restrict__ bih1, const float* __restrict__ bhh1) {
    int i = blockIdx.x * blockDim.x + threadIdx.x;
    if (i < BB * DD) {
        ((float*)g_h0)[i] = h0[i];
        ((float*)g_h1)[i] = h0[BB * DD + i];
        ((float*)g_c0)[i] = c0[i];
        ((float*)g_c1)[i] = c0[BB * DD + i];
        ((float*)g_out)[i] = io[i];
    }
    if (i < 4 * DD) {
        g_bias0[i] = bih0[i] + bhh0[i];
        g_bias1[i] = bih1[i] + bhh1[i];
    }
}

// ---------------- transpose W_in ----------------
__global__ void transpose_kernel(const float* __restrict__ Win) {
    __shared__ float tile[32][33];
    int bx = blockIdx.x * 32, by = blockIdx.y * 32;
    int x = threadIdx.x, y0 = threadIdx.y;  // blockDim (32,8)
    #pragma unroll
    for (int j = 0; j < 32; j += 8)
        tile[y0 + j][x] = Win[(size_t)(by + y0 + j) * DD + bx + x];
    __syncthreads();
    #pragma unroll
    for (int j = 0; j < 32; j += 8)
        g_WinT[(size_t)(bx + y0 + j) * DD + by + x] = tile[x][y0 + j];
}

// ---------------- Cq precompute (one-time): Cq[s][b][k] = ctx[s][b][:] . WinT[k][:]
__global__ __launch_bounds__(256, 1) void cq_kernel(const float* __restrict__ context) {
    __shared__ float ws[32][128];
    __shared__ float xs[32][64];
    const int tid = threadIdx.x;
    const int rowBase = blockIdx.x * 128;
    const int s = blockIdx.y;
    const int rg4 = (tid >> 3) << 2, b8 = (tid & 7) << 3;
    const int wrow = tid & 127, wkh = tid >> 7;
    const int xb = tid & 63, xkg = tid >> 6;

    ull acc[4][4];
    #pragma unroll
    for (int r = 0; r < 4; r++)
        #pragma unroll
        for (int p = 0; p < 4; p++) acc[r][p] = 0ull;

    for (int k0 = 0; k0 < DD; k0 += 32) {
        {
            const float* src = g_WinT + (size_t)(rowBase + wrow) * DD + k0 + wkh * 16;
            #pragma unroll
            for (int i = 0; i < 16; i += 4) {
                float4 v = *(const float4*)(src + i);
                ws[wkh * 16 + i + 0][wrow] = v.x;
                ws[wkh * 16 + i + 1][wrow] = v.y;
                ws[wkh * 16 + i + 2][wrow] = v.z;
                ws[wkh * 16 + i + 3][wrow] = v.w;
            }
        }
        {
            const float* src = context + (size_t)(s * BB + xb) * DD + k0 + xkg * 8;
            float4 v0 = *(const float4*)(src);
            float4 v1 = *(const float4*)(src + 4);
            xs[xkg * 8 + 0][xb] = v0.x; xs[xkg * 8 + 1][xb] = v0.y;
            xs[xkg * 8 + 2][xb] = v0.z; xs[xkg * 8 + 3][xb] = v0.w;
            xs[xkg * 8 + 4][xb] = v1.x; xs[xkg * 8 + 5][xb] = v1.y;
            xs[xkg * 8 + 6][xb] = v1.z; xs[xkg * 8 + 7][xb] = v1.w;
        }
        __syncthreads();
        #pragma unroll 8
        for (int kk = 0; kk < 32; kk++) {
            float4 wv = *(const float4*)&ws[kk][rg4];
            ull w0 = dup2(wv.x), w1 = dup2(wv.y), w2 = dup2(wv.z), w3 = dup2(wv.w);
            ulonglong2 xa = *(const ulonglong2*)&xs[kk][b8];
            ulonglong2 xc = *(const ulonglong2*)&xs[kk][b8 + 4];
            ffma2(acc[0][0], w0, xa.x); ffma2(acc[0][1], w0, xa.y);
            ffma2(acc[0][2], w0, xc.x); ffma2(acc[0][3], w0, xc.y);
            ffma2(acc[1][0], w1, xa.x); ffma2(acc[1][1], w1, xa.y);
            ffma2(acc[1][2], w1, xc.x); ffma2(acc[1][3], w1, xc.y);
            ffma2(acc[2][0], w2, xa.x); ffma2(acc[2][1], w2, xa.y);
            ffma2(acc[2][2], w2, xc.x); ffma2(acc[2][3], w2, xc.y);
            ffma2(acc[3][0], w3, xa.x); ffma2(acc[3][1], w3, xa.y);
            ffma2(acc[3][2], w3, xc.x); ffma2(acc[3][3], w3, xc.y);
        }
        __syncthreads();
    }
    #pragma unroll
    for (int r = 0; r < 4; r++) {
        int krow = rowBase + rg4 + r;
        #pragma unroll
        for (int p = 0; p < 4; p++) {
            float2 v = *(float2*)&acc[r][p];
            g_Cq[(size_t)(s * BB + b8 + 2 * p) * DD + krow]     = v.x;
            g_Cq[(size_t)(s * BB + b8 + 2 * p + 1) * DD + krow] = v.y;
        }
    }
}

// ---------------- shared-mem layout for the step kernel ----------------
struct SmemGemm {
    float ws[32][256];   // 32KB  weights tile [kk][row]
    float xs[32][64];    // 8KB   x tile [kk][b]
};
struct SmemAttn {
    float h1s[DD];       // 4KB
    float4 wbuf[4][128]; // 8KB   wctx partial reduce
};
union SmemU {
    SmemGemm g;
    SmemAttn a;
};

// ---------------- GEMM phase: tile 256 rows x 64 batch, 512 threads ----------------
// per-thread: 4 rows x 8 batches (16 f32x2 accumulators)
// modes: 0 = lstm0 x=[emb|out|h0], 1 = lstm1 x=[h0|h1], 3 = out x=[wctx|h1]
__device__ __forceinline__ void gemm_tile(
    int mode, int rowBase, int ksBase, int KS, int K1w,
    const float* __restrict__ W1, const float* __restrict__ W2,
    float* __restrict__ partOut,
    const float* __restrict__ word_lut, const int* toks, SmemGemm* sm) {
    const int tid = threadIdx.x;
    const int rg4 = (tid >> 3) << 2;     // 4 rows (0..252)
    const int b8  = (tid & 7) << 3;      // 8 batches
    const int wrow = tid & 255, wkh = tid >> 8;   // ws staging: 16 kk x 1 row
    const int xb = tid & 63, xkg = tid >> 6;      // xs staging: 4 kk x 1 b

    ull acc[4][4];
    #pragma unroll
    for (int r = 0; r < 4; r++)
        #pragma unroll
        for (int p = 0; p < 4; p++) acc[r][p] = 0ull;

    for (int k0 = ksBase; k0 < ksBase + KS; k0 += 32) {
        {
            int kb = k0 + wkh * 16;
            const float* src = (kb < K1w)
                ? W1 + (size_t)(rowBase + wrow) * K1w + kb
                : W2 + (size_t)(rowBase + wrow) * DD + (kb - K1w);
            #pragma unroll
            for (int i = 0; i < 16; i += 4) {
                float4 v = *(const float4*)(src + i);
                sm->ws[wkh * 16 + i + 0][wrow] = v.x;
                sm->ws[wkh * 16 + i + 1][wrow] = v.y;
                sm->ws[wkh * 16 + i + 2][wrow] = v.z;
                sm->ws[wkh * 16 + i + 3][wrow] = v.w;
            }
        }
        {
            int kb = k0 + xkg * 4;
            const float* src;
            if (mode == 0) {
                if (kb < EE)           src = word_lut + (size_t)toks[xb] * EE + kb;
                else if (kb < EE + DD) src = &g_out[xb][kb - EE];
                else                   src = &g_h0[xb][kb - (EE + DD)];
            } else if (mode == 1) {
                src = (kb < DD) ? &g_h0[xb][kb] : &g_h1[xb][kb - DD];
            } else {
                src = (kb < DD) ? &g_wctx[xb][kb] : &g_h1[xb][kb - DD];
            }
            float4 v = *(const float4*)(src);
            sm->xs[xkg * 4 + 0][xb] = v.x;
            sm->xs[xkg * 4 + 1][xb] = v.y;
            sm->xs[xkg * 4 + 2][xb] = v.z;
            sm->xs[xkg * 4 + 3][xb] = v.w;
        }
        __syncthreads();
        #pragma unroll 8
        for (int kk = 0; kk < 32; kk++) {
            float4 wv = *(const float4*)&sm->ws[kk][rg4];
            ull w0 = dup2(wv.x), w1 = dup2(wv.y), w2 = dup2(wv.z), w3 = dup2(wv.w);
            ulonglong2 xa = *(const ulonglong2*)&sm->xs[kk][b8];
            ulonglong2 xc = *(const ulonglong2*)&sm->xs[kk][b8 + 4];
            ffma2(acc[0][0], w0, xa.x); ffma2(acc[0][1], w0, xa.y);
            ffma2(acc[0][2], w0, xc.x); ffma2(acc[0][3], w0, xc.y);
            ffma2(acc[1][0], w1, xa.x); ffma2(acc[1][1], w1, xa.y);
            ffma2(acc[1][2], w1, xc.x); ffma2(acc[1][3], w1, xc.y);
            ffma2(acc[2][0], w2, xa.x); ffma2(acc[2][1], w2, xa.y);
            ffma2(acc[2][2], w2, xc.x); ffma2(acc[2][3], w2, xc.y);
            ffma2(acc[3][0], w3, xa.x); ffma2(acc[3][1], w3, xa.y);
            ffma2(acc[3][2], w3, xc.x); ffma2(acc[3][3], w3, xc.y);
        }
        __syncthreads();
    }
    #pragma unroll
    for (int r = 0; r < 4; r++) {
        float* p = partOut + (size_t)(rowBase + rg4 + r) * 64 + b8;
        *(ulonglong2*)(p)     = make_ulonglong2(acc[r][0], acc[r][1]);
        *(ulonglong2*)(p + 4) = make_ulonglong2(acc[r][2], acc[r][3]);
    }
}

__device__ __forceinline__ void cell_phase(int layer) {
    int e = blockIdx.x * NTHR + threadIdx.x;    // exactly 65536 = 128*512
    int b = e & 63, d = e >> 6;
    const float* bias = layer ? g_bias1 : g_bias0;
    float g[4];
    #pragma unroll
    for (int gate = 0; gate < 4; gate++) {
        int row = gate * DD + d;
        float s = bias[row];
        #pragma unroll
        for (int ks = 0; ks < 8; ks++)
            s += g_part[((size_t)ks * 4096 + row) * 64 + b];
        g[gate] = s;
    }
    if (layer) {
        float cn = sigm(g[1]) * g_c1[b][d] + sigm(g[0]) * tanhf(g[2]);
        g_c1[b][d] = cn;
        g_h1[b][d] = sigm(g[3]) * tanhf(cn);
    } else {
        float cn = sigm(g[1]) * g_c0[b][d] + sigm(g[0]) * tanhf(g[2]);
        g_c0[b][d] = cn;
        g_h0[b][d] = sigm(g[3]) * tanhf(cn);
    }
}

// 2 CTAs per batch: both compute scores+softmax; wctx d-range split by parity.
__device__ __forceinline__ void attn_phase(
    int t, const float* __restrict__ context, float* __restrict__ attns,
    SmemAttn* sm, float* sc, float* red) {
    const int tid = threadIdx.x;
    const int b = blockIdx.x >> 1;
    const int half = blockIdx.x & 1;
    const int lane = tid & 31, warp = tid >> 5;

    for (int i = tid; i < DD; i += NTHR) sm->h1s[i] = g_h1[b][i];
    __syncthreads();

    // scores: 16 warps x 8 scores each
    #pragma unroll
    for (int i = 0; i < 8; i++) {
        int s = warp + 16 * i;
        const float4* cp = (const float4*)(g_Cq + (size_t)(s * BB + b) * DD);
        float p = 0.f;
        #pragma unroll
        for (int j = 0; j < 8; j++) {
            int d4 = lane + j * 32;
            float4 v = cp[d4];
            p += v.x * sm->h1s[4 * d4] + v.y * sm->h1s[4 * d4 + 1] +
                 v.z * sm->h1s[4 * d4 + 2] + v.w * sm->h1s[4 * d4 + 3];
        }
        #pragma unroll
        for (int off = 16; off; off >>= 1) p += __shfl_xor_sync(~0u, p, off);
        if (lane == 0) sc[s] = p;
    }
    __syncthreads();

    float v = (tid < 128) ? sc[tid] : -1e30f;
    float m = v;
    #pragma unroll
    for (int off = 16; off; off >>= 1) m = fmaxf(m, __shfl_xor_sync(~0u, m, off));
    if (tid < 128 && lane == 0) red[warp] = m;
    __syncthreads();
    m = fmaxf(fmaxf(red[0], red[1]), fmaxf(red[2], red[3]));
    float ex = (tid < 128) ? __expf(v - m) : 0.f;
    float ssum = ex;
    #pragma unroll
    for (int off = 16; off; off >>= 1) ssum += __shfl_xor_sync(~0u, ssum, off);
    if (tid < 128 && lane == 0) red[4 + warp] = ssum;
    __syncthreads();
    ssum = red[4] + red[5] + red[6] + red[7];
    if (tid < 128) {
        float a = ex / ssum;
        sc[tid] = a;
        if (half == 0) attns[((size_t)b * TT + t) * SS + tid] = a;
    }
    __syncthreads();

    // wctx for d in [half*512, half*512+512): 4 s-groups x 128 d4-columns
    const int g = tid >> 7, j = tid & 127;
    const int d4 = half * 512 + j * 4;
    float4 a4 = make_float4(0.f, 0.f, 0.f, 0.f);
    #pragma unroll 4
    for (int s = g * 32; s < g * 32 + 32; s++) {
        float as = sc[s];
        float4 vv = *(const float4*)(context + (size_t)(s * BB + b) * DD + d4);
        a4.x += as * vv.x; a4.y += as * vv.y; a4.z += as * vv.z; a4.w += as * vv.w;
    }
    sm->wbuf[g][j] = a4;
    __syncthreads();
    if (g == 0) {
        float4 r0 = sm->wbuf[0][j], r1 = sm->wbuf[1][j], r2 = sm->wbuf[2][j], r3 = sm->wbuf[3][j];
        float4 o = make_float4(r0.x + r1.x + r2.x + r3.x, r0.y + r1.y + r2.y + r3.y,
                               r0.z + r1.z + r2.z + r3.z, r0.w + r1.w + r2.w + r3.w);
        *(float4*)&g_wctx[b][d4] = o;
    }
    __syncthreads();
}

__device__ __forceinline__ void outred_phase(int t, float* __restrict__ outs) {
    int e = blockIdx.x * NTHR + threadIdx.x;    // 65536
    int b = e & 63, d = e >> 6;
    float s = 0.f;
    #pragma unroll
    for (int ks = 0; ks < 32; ks++)
        s += g_part[((size_t)ks * 1024 + d) * 64 + b];
    float v = tanhf(s);
    g_out[b][d] = v;
    outs[((size_t)b * TT + t) * DD + d] = v;
}

// ---------------- one timestep = one kernel ----------------
__global__ __launch_bounds__(NTHR, 1) void step_kernel(
    int t, const int* __restrict__ input,
    const float* __restrict__ word_lut,
    const float* __restrict__ Wih0, const float* __restrict__ Whh0,
    const float* __restrict__ Wih1, const float* __restrict__ Whh1,
    const float* __restrict__ Wout,
    const float* __restrict__ context,
    float* __restrict__ outs, float* __restrict__ attns) {
    __shared__ SmemU sm;
    __shared__ int toks[64];
    __shared__ float sc[SS];
    __shared__ float red[8];

    const int tid = threadIdx.x;
    const int bid = blockIdx.x;
    if (tid < 64) toks[tid] = input[tid * TT + t];
    __syncthreads();

    // lstm0 gates: 4096 rows -> 16 rowtiles(256) x 8 ksplit (KS=320)
    gemm_tile(0, (bid & 15) * 256, (bid >> 4) * 320, 320, EE + DD,
              Wih0, Whh0, g_part + (size_t)(bid >> 4) * 4096 * 64,
              word_lut, toks, &sm.g);
    grid_barrier();
    cell_phase(0);
    grid_barrier();
    // lstm1 gates: 4096 rows -> 16 rowtiles x 8 ksplit (KS=256)
    gemm_tile(1, (bid & 15) * 256, (bid >> 4) * 256, 256, DD,
              Wih1, Whh1, g_part + (size_t)(bid >> 4) * 4096 * 64,
              word_lut, toks, &sm.g);
    grid_barrier();
    cell_phase(1);
    grid_barrier();
    attn_phase(t, context, attns, &sm.a, sc, red);
    grid_barrier();
    // out gemm: 1024 rows -> 4 rowtiles x 32 ksplit (KS=64)
    gemm_tile(3, (bid & 3) * 256, (bid >> 2) * 64, 64, 2 * DD,
              Wout, Wout, g_part + (size_t)(bid >> 2) * 1024 * 64,
              word_lut, toks, &sm.g);
    grid_barrier();
    outred_phase(t, outs);
}

// ---------------- final ----------------
__global__ void final_kernel(float* __restrict__ hout, float* __restrict__ cout) {
    int i = blockIdx.x * blockDim.x + threadIdx.x;
    if (i < BB * DD) {
        hout[i]           = ((float*)g_h0)[i];
        hout[BB * DD + i] = ((float*)g_h1)[i];
        cout[i]           = ((float*)g_c0)[i];
        cout[BB * DD + i] = ((float*)g_c1)[i];
    }
}

// ---------------- launch ----------------
extern "C" void kernel_launch(void* const* d_in, const int* in_sizes, int n_in,
                              void* d_out, int out_size) {
    const int*   input    = (const int*)d_in[0];
    const float* h0       = (const float*)d_in[2];
    const float* c0       = (const float*)d_in[3];
    const float* context  = (const float*)d_in[4];
    const float* init_out = (const float*)d_in[5];
    const float* word_lut = (const float*)d_in[6];
    const float* Wih0 = (const float*)d_in[7];
    const float* Whh0 = (const float*)d_in[8];
    const float* bih0 = (const float*)d_in[9];
    const float* bhh0 = (const float*)d_in[10];
    const float* Wih1 = (const float*)d_in[11];
    const float* Whh1 = (const float*)d_in[12];
    const float* bih1 = (const float*)d_in[13];
    const float* bhh1 = (const float*)d_in[14];
    const float* Win  = (const float*)d_in[15];
    const float* Wout = (const float*)d_in[16];

    float* out   = (float*)d_out;
    float* outs  = out;                           // [B,T,D]
    float* hout  = out + (size_t)BB * TT * DD;    // [2,B,D]
    float* cout  = hout + 2 * BB * DD;            // [2,B,D]
    float* attns = cout + 2 * BB * DD;            // [B,T,S]

    init_kernel<<<256, 256>>>(h0, c0, init_out, bih0, bhh0, bih1, bhh1);
    transpose_kernel<<<dim3(32, 32), dim3(32, 8)>>>(Win);
    cq_kernel<<<dim3(8, 128), 256>>>(context);
    for (int t = 0; t < TT; t++) {
        step_kernel<<<NCTA, NTHR>>>(t, input, word_lut, Wih0, Whh0, Wih1, Whh1,
                                    Wout, context, outs, attns);
    }
    final_kernel<<<256, 256>>>(hout, cout);
}

// round 6
// speedup vs baseline: 5.6205x; 1.8347x over previous
#include <cuda_runtime.h>
#include <math.h>

#define BB 64
#define DD 1024
#define TT 128
#define SS 128
#define EE 512
#define NCTA 128
#define NTHR 512

typedef unsigned long long ull;

// ---------------- device scratch (static, no allocations) ----------------
__device__ float g_h0[BB][DD];
__device__ float g_h1[BB][DD];
__device__ float g_c0[BB][DD];
__device__ float g_c1[BB][DD];
__device__ float g_out[BB][DD];
__device__ float g_wctx[BB][DD];
__device__ float g_bias0[4 * DD];
__device__ float g_bias1[4 * DD];
__device__ float g_WinT[DD * DD];                 // W_in transposed
__device__ float g_Cq[(size_t)SS * BB * DD];      // ctx @ W_in : [s][b][k]
__device__ float g_part[8 * 4096 * 64];           // split-K partials (8MB)

__device__ unsigned g_bar_count;
__device__ volatile unsigned g_bar_epoch;

__device__ __forceinline__ float sigm(float x) { return 1.f / (1.f + __expf(-x)); }

__device__ __forceinline__ void ffma2(ull &d, ull a, ull b) {
    asm("fma.rn.f32x2 %0, %1, %2, %0;" : "+l"(d) : "l"(a), "l"(b));
}
__device__ __forceinline__ ull dup2(float w) {
    ull r; asm("mov.b64 %0, {%1, %1};" : "=l"(r) : "f"(w)); return r;
}
__device__ __forceinline__ unsigned tf32c(float x) {
    unsigned r; asm("cvt.rna.tf32.f32 %0, %1;" : "=r"(r) : "f"(x)); return r;
}
__device__ __forceinline__ void mma_tf32(float* c, const unsigned* a, const unsigned* b) {
    asm volatile(
        "mma.sync.aligned.m16n8k8.row.col.f32.tf32.tf32.f32 "
        "{%0,%1,%2,%3}, {%4,%5,%6,%7}, {%8,%9}, {%0,%1,%2,%3};"
        : "+f"(c[0]), "+f"(c[1]), "+f"(c[2]), "+f"(c[3])
        : "r"(a[0]), "r"(a[1]), "r"(a[2]), "r"(a[3]), "r"(b[0]), "r"(b[1]));
}

// software grid barrier (128 CTAs, all resident)
__device__ __forceinline__ void grid_barrier() {
    __syncthreads();
    if (threadIdx.x == 0) {
        unsigned e = g_bar_epoch;
        __threadfence();
        unsigned a = atomicAdd(&g_bar_count, 1u);
        if (a == NCTA - 1) {
            g_bar_count = 0;
            __threadfence();
            atomicAdd((unsigned*)&g_bar_epoch, 1u);
        } else {
            while (g_bar_epoch == e) { __nanosleep(32); }
        }
        __threadfence();
    }
    __syncthreads();
}

// ---------------- init ----------------
__global__ void init_kernel(const float* __restrict__ h0, const float* __restrict__ c0,
                            const float* __restrict__ io,
                            const float* __restrict__ bih0, const float* __restrict__ bhh0,
                            const float* __restrict__ bih1, const float* __restrict__ bhh1) {
    int i = blockIdx.x * blockDim.x + threadIdx.x;
    if (i < BB * DD) {
        ((float*)g_h0)[i] = h0[i];
        ((float*)g_h1)[i] = h0[BB * DD + i];
        ((float*)g_c0)[i] = c0[i];
        ((float*)g_c1)[i] = c0[BB * DD + i];
        ((float*)g_out)[i] = io[i];
    }
    if (i < 4 * DD) {
        g_bias0[i] = bih0[i] + bhh0[i];
        g_bias1[i] = bih1[i] + bhh1[i];
    }
}

// ---------------- transpose W_in ----------------
__global__ void transpose_kernel(const float* __restrict__ Win) {
    __shared__ float tile[32][33];
    int bx = blockIdx.x * 32, by = blockIdx.y * 32;
    int x = threadIdx.x, y0 = threadIdx.y;  // blockDim (32,8)
    #pragma unroll
    for (int j = 0; j < 32; j += 8)
        tile[y0 + j][x] = Win[(size_t)(by + y0 + j) * DD + bx + x];
    __syncthreads();
    #pragma unroll
    for (int j = 0; j < 32; j += 8)
        g_WinT[(size_t)(bx + y0 + j) * DD + by + x] = tile[x][y0 + j];
}

// ---------------- Cq precompute (one-time, fp32 FFMA2): Cq[s][b][k] = ctx[s][b][:].WinT[k][:]
__global__ __launch_bounds__(256, 1) void cq_kernel(const float* __restrict__ context) {
    __shared__ float ws[32][128];
    __shared__ float xs[32][64];
    const int tid = threadIdx.x;
    const int rowBase = blockIdx.x * 128;
    const int s = blockIdx.y;
    const int rg4 = (tid >> 3) << 2, b8 = (tid & 7) << 3;
    const int wrow = tid & 127, wkh = tid >> 7;
    const int xb = tid & 63, xkg = tid >> 6;

    ull acc[4][4];
    #pragma unroll
    for (int r = 0; r < 4; r++)
        #pragma unroll
        for (int p = 0; p < 4; p++) acc[r][p] = 0ull;

    for (int k0 = 0; k0 < DD; k0 += 32) {
        {
            const float* src = g_WinT + (size_t)(rowBase + wrow) * DD + k0 + wkh * 16;
            #pragma unroll
            for (int i = 0; i < 16; i += 4) {
                float4 v = *(const float4*)(src + i);
                ws[wkh * 16 + i + 0][wrow] = v.x;
                ws[wkh * 16 + i + 1][wrow] = v.y;
                ws[wkh * 16 + i + 2][wrow] = v.z;
                ws[wkh * 16 + i + 3][wrow] = v.w;
            }
        }
        {
            const float* src = context + (size_t)(s * BB + xb) * DD + k0 + xkg * 8;
            float4 v0 = *(const float4*)(src);
            float4 v1 = *(const float4*)(src + 4);
            xs[xkg * 8 + 0][xb] = v0.x; xs[xkg * 8 + 1][xb] = v0.y;
            xs[xkg * 8 + 2][xb] = v0.z; xs[xkg * 8 + 3][xb] = v0.w;
            xs[xkg * 8 + 4][xb] = v1.x; xs[xkg * 8 + 5][xb] = v1.y;
            xs[xkg * 8 + 6][xb] = v1.z; xs[xkg * 8 + 7][xb] = v1.w;
        }
        __syncthreads();
        #pragma unroll 8
        for (int kk = 0; kk < 32; kk++) {
            float4 wv = *(const float4*)&ws[kk][rg4];
            ull w0 = dup2(wv.x), w1 = dup2(wv.y), w2 = dup2(wv.z), w3 = dup2(wv.w);
            ulonglong2 xa = *(const ulonglong2*)&xs[kk][b8];
            ulonglong2 xc = *(const ulonglong2*)&xs[kk][b8 + 4];
            ffma2(acc[0][0], w0, xa.x); ffma2(acc[0][1], w0, xa.y);
            ffma2(acc[0][2], w0, xc.x); ffma2(acc[0][3], w0, xc.y);
            ffma2(acc[1][0], w1, xa.x); ffma2(acc[1][1], w1, xa.y);
            ffma2(acc[1][2], w1, xc.x); ffma2(acc[1][3], w1, xc.y);
            ffma2(acc[2][0], w2, xa.x); ffma2(acc[2][1], w2, xa.y);
            ffma2(acc[2][2], w2, xc.x); ffma2(acc[2][3], w2, xc.y);
            ffma2(acc[3][0], w3, xa.x); ffma2(acc[3][1], w3, xa.y);
            ffma2(acc[3][2], w3, xc.x); ffma2(acc[3][3], w3, xc.y);
        }
        __syncthreads();
    }
    #pragma unroll
    for (int r = 0; r < 4; r++) {
        int krow = rowBase + rg4 + r;
        #pragma unroll
        for (int p = 0; p < 4; p++) {
            float2 v = *(float2*)&acc[r][p];
            g_Cq[(size_t)(s * BB + b8 + 2 * p) * DD + krow]     = v.x;
            g_Cq[(size_t)(s * BB + b8 + 2 * p + 1) * DD + krow] = v.y;
        }
    }
}

// ---------------- shared-mem layouts ----------------
struct SmemGemm {
    unsigned ws[16][4][32][4];   // 32KB  A frags [mblock][k8][lane][reg]
    unsigned xs[8][4][32][2];    // 8KB   B frags [nblock][k8][lane][reg]
};
struct SmemAttn {
    float h1s[DD];       // 4KB
    float4 wbuf[4][128]; // 8KB
};
union SmemU {
    SmemGemm g;
    SmemAttn a;
};

// x element pointer for GEMM B operand (logical x[k][b], stored [b][k])
__device__ __forceinline__ const float* xptr(int mode, int b, int k,
                                             const int* toks, const float* word_lut) {
    if (mode == 0) {
        if (k < EE) return word_lut + (size_t)toks[b] * EE + k;
        if (k < EE + DD) return &g_out[b][k - EE];
        return &g_h0[b][k - (EE + DD)];
    } else if (mode == 1) {
        return (k < DD) ? &g_h0[b][k] : &g_h1[b][k - DD];
    }
    return (k < DD) ? &g_wctx[b][k] : &g_h1[b][k - DD];
}

// ---------------- tf32 tensor-core GEMM phase ----------------
// CTA tile 256 rows x 64 batch; 16 warps (8m x 2n), warp tile 32x32.
// partOut[row][b] += W[rowBase+row, ksBase:ksBase+KS] . x[., b]
__device__ __forceinline__ void gemm_tf32(
    int mode, int rowBase, int ksBase, int KS, int K1w,
    const float* __restrict__ W1, const float* __restrict__ W2,
    float* __restrict__ partOut,
    const float* __restrict__ word_lut, const int* toks, SmemGemm* sm) {
    const int tid = threadIdx.x;
    const int wid = tid >> 5, lane = tid & 31;
    const int g = lane >> 2, t = lane & 3;
    const int mb0 = (wid >> 1) << 1;   // 2 m-blocks of 16 rows
    const int nb0 = (wid & 1) << 2;    // 4 n-blocks of 8 batches

    float acc[2][4][4];
    #pragma unroll
    for (int i = 0; i < 2; i++)
        #pragma unroll
        for (int j = 0; j < 4; j++)
            #pragma unroll
            for (int r = 0; r < 4; r++) acc[i][j][r] = 0.f;

    float pa[4][4];   // A prefetch: 4 slots x regs {a0,a1,a2,a3}
    float pb[2][2];   // B prefetch: 2 slots x regs {b0,b1}

    // prefetch first chunk
    #pragma unroll
    for (int j = 0; j < 4; j++) {
        int mbk = j * 16 + wid, mb = mbk >> 2, k8 = mbk & 3;
        int row = rowBase + mb * 16 + g;
        int c = ksBase + k8 * 8 + t;
        const float* s0 = (c < K1w) ? W1 + (size_t)row * K1w + c : W2 + (size_t)row * DD + (c - K1w);
        const float* s1 = (c < K1w) ? W1 + (size_t)(row + 8) * K1w + c : W2 + (size_t)(row + 8) * DD + (c - K1w);
        pa[j][0] = s0[0]; pa[j][1] = s1[0]; pa[j][2] = s0[4]; pa[j][3] = s1[4];
    }
    #pragma unroll
    for (int j = 0; j < 2; j++) {
        int nbk = j * 16 + wid, nb = nbk >> 2, k8 = nbk & 3;
        int b = nb * 8 + g;
        int k = ksBase + k8 * 8 + t;
        const float* s = xptr(mode, b, k, toks, word_lut);
        pb[j][0] = s[0]; pb[j][1] = s[4];
    }

    for (int k0 = ksBase; k0 < ksBase + KS; k0 += 32) {
        __syncthreads();
        // store staged fragments (cvt to tf32); lane-contiguous -> conflict-free
        #pragma unroll
        for (int j = 0; j < 4; j++) {
            int mbk = j * 16 + wid, mb = mbk >> 2, k8 = mbk & 3;
            *(uint4*)&sm->ws[mb][k8][lane][0] =
                make_uint4(tf32c(pa[j][0]), tf32c(pa[j][1]), tf32c(pa[j][2]), tf32c(pa[j][3]));
        }
        #pragma unroll
        for (int j = 0; j < 2; j++) {
            int nbk = j * 16 + wid, nb = nbk >> 2, k8 = nbk & 3;
            *(uint2*)&sm->xs[nb][k8][lane][0] = make_uint2(tf32c(pb[j][0]), tf32c(pb[j][1]));
        }
        __syncthreads();

        // prefetch next chunk while MMAs run
        int kn = k0 + 32;
        if (kn < ksBase + KS) {
            #pragma unroll
            for (int j = 0; j < 4; j++) {
                int mbk = j * 16 + wid, mb = mbk >> 2, k8 = mbk & 3;
                int row = rowBase + mb * 16 + g;
                int c = kn + k8 * 8 + t;
                const float* s0 = (c < K1w) ? W1 + (size_t)row * K1w + c : W2 + (size_t)row * DD + (c - K1w);
                const float* s1 = (c < K1w) ? W1 + (size_t)(row + 8) * K1w + c : W2 + (size_t)(row + 8) * DD + (c - K1w);
                pa[j][0] = s0[0]; pa[j][1] = s1[0]; pa[j][2] = s0[4]; pa[j][3] = s1[4];
            }
            #pragma unroll
            for (int j = 0; j < 2; j++) {
                int nbk = j * 16 + wid, nb = nbk >> 2, k8 = nbk & 3;
                int b = nb * 8 + g;
                int k = kn + k8 * 8 + t;
                const float* s = xptr(mode, b, k, toks, word_lut);
                pb[j][0] = s[0]; pb[j][1] = s[4];
            }
        }

        // compute: 4 k8 steps x (2m x 4n) mma
        #pragma unroll
        for (int k8 = 0; k8 < 4; k8++) {
            uint4 a0 = *(const uint4*)&sm->ws[mb0][k8][lane][0];
            uint4 a1 = *(const uint4*)&sm->ws[mb0 + 1][k8][lane][0];
            #pragma unroll
            for (int nj = 0; nj < 4; nj++) {
                uint2 bb = *(const uint2*)&sm->xs[nb0 + nj][k8][lane][0];
                mma_tf32(acc[0][nj], (const unsigned*)&a0, (const unsigned*)&bb);
                mma_tf32(acc[1][nj], (const unsigned*)&a1, (const unsigned*)&bb);
            }
        }
    }

    // epilogue: write fp32 partials
    #pragma unroll
    for (int mi = 0; mi < 2; mi++) {
        int rb = rowBase + (mb0 + mi) * 16 + g;
        #pragma unroll
        for (int nj = 0; nj < 4; nj++) {
            int col = (nb0 + nj) * 8 + 2 * t;
            *(float2*)&partOut[(size_t)rb * 64 + col]       = make_float2(acc[mi][nj][0], acc[mi][nj][1]);
            *(float2*)&partOut[(size_t)(rb + 8) * 64 + col] = make_float2(acc[mi][nj][2], acc[mi][nj][3]);
        }
    }
}

__device__ __forceinline__ void cell_phase(int layer) {
    int e = blockIdx.x * NTHR + threadIdx.x;    // 65536 = 128*512
    int b = e & 63, d = e >> 6;
    const float* bias = layer ? g_bias1 : g_bias0;
    float g[4];
    #pragma unroll
    for (int gate = 0; gate < 4; gate++) {
        int row = gate * DD + d;
        float s = bias[row];
        #pragma unroll
        for (int ks = 0; ks < 8; ks++)
            s += g_part[((size_t)ks * 4096 + row) * 64 + b];
        g[gate] = s;
    }
    if (layer) {
        float cn = sigm(g[1]) * g_c1[b][d] + sigm(g[0]) * tanhf(g[2]);
        g_c1[b][d] = cn;
        g_h1[b][d] = sigm(g[3]) * tanhf(cn);
    } else {
        float cn = sigm(g[1]) * g_c0[b][d] + sigm(g[0]) * tanhf(g[2]);
        g_c0[b][d] = cn;
        g_h0[b][d] = sigm(g[3]) * tanhf(cn);
    }
}

// 2 CTAs per batch; wctx d-range split by CTA parity.
__device__ __forceinline__ void attn_phase(
    int t, const float* __restrict__ context, float* __restrict__ attns,
    SmemAttn* sm, float* sc, float* red) {
    const int tid = threadIdx.x;
    const int b = blockIdx.x >> 1;
    const int half = blockIdx.x & 1;
    const int lane = tid & 31, warp = tid >> 5;

    for (int i = tid; i < DD; i += NTHR) sm->h1s[i] = g_h1[b][i];
    __syncthreads();

    #pragma unroll
    for (int i = 0; i < 8; i++) {
        int s = warp + 16 * i;
        const float4* cp = (const float4*)(g_Cq + (size_t)(s * BB + b) * DD);
        float p = 0.f;
        #pragma unroll
        for (int j = 0; j < 8; j++) {
            int d4 = lane + j * 32;
            float4 v = cp[d4];
            p += v.x * sm->h1s[4 * d4] + v.y * sm->h1s[4 * d4 + 1] +
                 v.z * sm->h1s[4 * d4 + 2] + v.w * sm->h1s[4 * d4 + 3];
        }
        #pragma unroll
        for (int off = 16; off; off >>= 1) p += __shfl_xor_sync(~0u, p, off);
        if (lane == 0) sc[s] = p;
    }
    __syncthreads();

    float v = (tid < 128) ? sc[tid] : -1e30f;
    float m = v;
    #pragma unroll
    for (int off = 16; off; off >>= 1) m = fmaxf(m, __shfl_xor_sync(~0u, m, off));
    if (tid < 128 && lane == 0) red[warp] = m;
    __syncthreads();
    m = fmaxf(fmaxf(red[0], red[1]), fmaxf(red[2], red[3]));
    float ex = (tid < 128) ? __expf(v - m) : 0.f;
    float ssum = ex;
    #pragma unroll
    for (int off = 16; off; off >>= 1) ssum += __shfl_xor_sync(~0u, ssum, off);
    if (tid < 128 && lane == 0) red[4 + warp] = ssum;
    __syncthreads();
    ssum = red[4] + red[5] + red[6] + red[7];
    if (tid < 128) {
        float a = ex / ssum;
        sc[tid] = a;
        if (half == 0) attns[((size_t)b * TT + t) * SS + tid] = a;
    }
    __syncthreads();

    const int g = tid >> 7, j = tid & 127;
    const int d4 = half * 512 + j * 4;
    float4 a4 = make_float4(0.f, 0.f, 0.f, 0.f);
    #pragma unroll 4
    for (int s = g * 32; s < g * 32 + 32; s++) {
        float as = sc[s];
        float4 vv = *(const float4*)(context + (size_t)(s * BB + b) * DD + d4);
        a4.x += as * vv.x; a4.y += as * vv.y; a4.z += as * vv.z; a4.w += as * vv.w;
    }
    sm->wbuf[g][j] = a4;
    __syncthreads();
    if (g == 0) {
        float4 r0 = sm->wbuf[0][j], r1 = sm->wbuf[1][j], r2 = sm->wbuf[2][j], r3 = sm->wbuf[3][j];
        float4 o = make_float4(r0.x + r1.x + r2.x + r3.x, r0.y + r1.y + r2.y + r3.y,
                               r0.z + r1.z + r2.z + r3.z, r0.w + r1.w + r2.w + r3.w);
        *(float4*)&g_wctx[b][d4] = o;
    }
    __syncthreads();
}

__device__ __forceinline__ void outred_phase(int t, float* __restrict__ outs) {
    int e = blockIdx.x * NTHR + threadIdx.x;    // 65536
    int b = e & 63, d = e >> 6;
    float s = 0.f;
    #pragma unroll
    for (int ks = 0; ks < 32; ks++)
        s += g_part[((size_t)ks * 1024 + d) * 64 + b];
    float v = tanhf(s);
    g_out[b][d] = v;
    outs[((size_t)b * TT + t) * DD + d] = v;
}

// ---------------- one timestep = one kernel ----------------
__global__ __launch_bounds__(NTHR, 1) void step_kernel(
    int t, const int* __restrict__ input,
    const float* __restrict__ word_lut,
    const float* __restrict__ Wih0, const float* __restrict__ Whh0,
    const float* __restrict__ Wih1, const float* __restrict__ Whh1,
    const float* __restrict__ Wout,
    const float* __restrict__ context,
    float* __restrict__ outs, float* __restrict__ attns) {
    __shared__ SmemU sm;
    __shared__ int toks[64];
    __shared__ float sc[SS];
    __shared__ float red[8];

    const int tid = threadIdx.x;
    const int bid = blockIdx.x;
    if (tid < 64) toks[tid] = input[tid * TT + t];
    __syncthreads();

    // lstm0 gates: 4096 rows -> 16 rowtiles(256) x 8 ksplit (KS=320)
    gemm_tf32(0, (bid & 15) * 256, (bid >> 4) * 320, 320, EE + DD,
              Wih0, Whh0, g_part + (size_t)(bid >> 4) * 4096 * 64,
              word_lut, toks, &sm.g);
    grid_barrier();
    cell_phase(0);
    grid_barrier();
    // lstm1 gates: 4096 rows -> 16 rowtiles x 8 ksplit (KS=256)
    gemm_tf32(1, (bid & 15) * 256, (bid >> 4) * 256, 256, DD,
              Wih1, Whh1, g_part + (size_t)(bid >> 4) * 4096 * 64,
              word_lut, toks, &sm.g);
    grid_barrier();
    cell_phase(1);
    grid_barrier();
    attn_phase(t, context, attns, &sm.a, sc, red);
    grid_barrier();
    // out gemm: 1024 rows -> 4 rowtiles x 32 ksplit (KS=64)
    gemm_tf32(3, (bid & 3) * 256, (bid >> 2) * 64, 64, 2 * DD,
              Wout, Wout, g_part + (size_t)(bid >> 2) * 1024 * 64,
              word_lut, toks, &sm.g);
    grid_barrier();
    outred_phase(t, outs);
}

// ---------------- final ----------------
__global__ void final_kernel(float* __restrict__ hout, float* __restrict__ cout) {
    int i = blockIdx.x * blockDim.x + threadIdx.x;
    if (i < BB * DD) {
        hout[i]           = ((float*)g_h0)[i];
        hout[BB * DD + i] = ((float*)g_h1)[i];
        cout[i]           = ((float*)g_c0)[i];
        cout[BB * DD + i] = ((float*)g_c1)[i];
    }
}

// ---------------- launch ----------------
extern "C" void kernel_launch(void* const* d_in, const int* in_sizes, int n_in,
                              void* d_out, int out_size) {
    const int*   input    = (const int*)d_in[0];
    const float* h0       = (const float*)d_in[2];
    const float* c0       = (const float*)d_in[3];
    const float* context  = (const float*)d_in[4];
    const float* init_out = (const float*)d_in[5];
    const float* word_lut = (const float*)d_in[6];
    const float* Wih0 = (const float*)d_in[7];
    const float* Whh0 = (const float*)d_in[8];
    const float* bih0 = (const float*)d_in[9];
    const float* bhh0 = (const float*)d_in[10];
    const float* Wih1 = (const float*)d_in[11];
    const float* Whh1 = (const float*)d_in[12];
    const float* bih1 = (const float*)d_in[13];
    const float* bhh1 = (const float*)d_in[14];
    const float* Win  = (const float*)d_in[15];
    const float* Wout = (const float*)d_in[16];

    float* out   = (float*)d_out;
    float* outs  = out;                           // [B,T,D]
    float* hout  = out + (size_t)BB * TT * DD;    // [2,B,D]
    float* cout  = hout + 2 * BB * DD;            // [2,B,D]
    float* attns = cout + 2 * BB * DD;            // [B,T,S]

    init_kernel<<<256, 256>>>(h0, c0, init_out, bih0, bhh0, bih1, bhh1);
    transpose_kernel<<<dim3(32, 32), dim3(32, 8)>>>(Win);
    cq_kernel<<<dim3(8, 128), 256>>>(context);
    for (int t = 0; t < TT; t++) {
        step_kernel<<<NCTA, NTHR>>>(t, input, word_lut, Wih0, Whh0, Wih1, Whh1,
                                    Wout, context, outs, attns);
    }
    final_kernel<<<256, 256>>>(hout, cout);
}

// round 9
// speedup vs baseline: 7.4305x; 1.3220x over previous
#include <cuda_runtime.h>
#include <math.h>

#define BB 64
#define DD 1024
#define TT 128
#define SS 128
#define EE 512
#define NCTA 128
#define NTHR 512

typedef unsigned long long ull;

// ---------------- device scratch (static, no allocations) ----------------
__device__ float g_h0[BB][DD];
__device__ float g_h1[BB][DD];
__device__ float g_c0[BB][DD];
__device__ float g_c1[BB][DD];
__device__ float g_out[BB][DD];
__device__ float g_wctx[BB][DD];
__device__ float g_bias0[4 * DD];
__device__ float g_bias1[4 * DD];
__device__ float g_WinT[DD * DD];
__device__ float g_Cq[(size_t)SS * BB * DD];            // ctx @ W_in : [s][b][k]
__device__ float g_part[8 * 4096 * 64];                 // split-K partials
__device__ float g_pre[(size_t)TT * 4096 * BB];         // emb projection [t][row][b]

// pre-packed tf32 fragment weights: idx = ((mb*K8 + k8)*32 + lane)
__device__ uint4 g_WfE[256 * 64 * 32];    // lstm0 emb part:  4096 x 512
__device__ uint4 g_Wf0[256 * 256 * 32];   // lstm0 [out|h0]:  4096 x 2048
__device__ uint4 g_Wf1[256 * 256 * 32];   // lstm1 [h0|h1]:   4096 x 2048
__device__ uint4 g_WfO[64 * 256 * 32];    // out  [wctx|h1]:  1024 x 2048

__device__ unsigned g_bar_count;
__device__ volatile unsigned g_bar_epoch;

__device__ __forceinline__ float sigm(float x) { return 1.f / (1.f + __expf(-x)); }

__device__ __forceinline__ void ffma2(ull &d, ull a, ull b) {
    asm("fma.rn.f32x2 %0, %1, %2, %0;" : "+l"(d) : "l"(a), "l"(b));
}
__device__ __forceinline__ ull dup2(float w) {
    ull r; asm("mov.b64 %0, {%1, %1};" : "=l"(r) : "f"(w)); return r;
}
__device__ __forceinline__ unsigned tf32c(float x) {
    unsigned r; asm("cvt.rna.tf32.f32 %0, %1;" : "=r"(r) : "f"(x)); return r;
}
__device__ __forceinline__ void mma_tf32(float* c, const unsigned* a, const unsigned* b) {
    asm volatile(
        "mma.sync.aligned.m16n8k8.row.col.f32.tf32.tf32.f32 "
        "{%0,%1,%2,%3}, {%4,%5,%6,%7}, {%8,%9}, {%0,%1,%2,%3};"
        : "+f"(c[0]), "+f"(c[1]), "+f"(c[2]), "+f"(c[3])
        : "r"(a[0]), "r"(a[1]), "r"(a[2]), "r"(a[3]), "r"(b[0]), "r"(b[1]));
}

// software grid barrier (128 CTAs, all resident)
__device__ __forceinline__ void grid_barrier() {
    __syncthreads();
    if (threadIdx.x == 0) {
        unsigned e = g_bar_epoch;
        __threadfence();
        unsigned a = atomicAdd(&g_bar_count, 1u);
        if (a == NCTA - 1) {
            g_bar_count = 0;
            __threadfence();
            atomicAdd((unsigned*)&g_bar_epoch, 1u);
        } else {
            while (g_bar_epoch == e) { __nanosleep(32); }
        }
        __threadfence();
    }
    __syncthreads();
}

// ---------------- shared-mem layouts ----------------
struct SmemGemm {
    uint4 A[3][16][4][32];   // 96KB  A frags, 3-stage
    uint2 Bf[2][8][4][32];   // 16KB  B frags, 2-stage
};
struct SmemAttn {
    float h1s[DD];
    float4 wbuf[4][128];
};
union SmemU {
    SmemGemm g;
    SmemAttn a;
};

// ---------------- init ----------------
__global__ void init_kernel(const float* __restrict__ h0, const float* __restrict__ c0,
                            const float* __restrict__ io,
                            const float* __restrict__ bih0, const float* __restrict__ bhh0,
                            const float* __restrict__ bih1, const float* __restrict__ bhh1) {
    int i = blockIdx.x * blockDim.x + threadIdx.x;
    if (i < BB * DD) {
        ((float*)g_h0)[i] = h0[i];
        ((float*)g_h1)[i] = h0[BB * DD + i];
        ((float*)g_c0)[i] = c0[i];
        ((float*)g_c1)[i] = c0[BB * DD + i];
        ((float*)g_out)[i] = io[i];
    }
    if (i < 4 * DD) {
        g_bias0[i] = bih0[i] + bhh0[i];
        g_bias1[i] = bih1[i] + bhh1[i];
    }
}

// ---------------- transpose W_in (for Cq) ----------------
__global__ void transpose_kernel(const float* __restrict__ Win) {
    __shared__ float tile[32][33];
    int bx = blockIdx.x * 32, by = blockIdx.y * 32;
    int x = threadIdx.x, y0 = threadIdx.y;
    #pragma unroll
    for (int j = 0; j < 32; j += 8)
        tile[y0 + j][x] = Win[(size_t)(by + y0 + j) * DD + bx + x];
    __syncthreads();
    #pragma unroll
    for (int j = 0; j < 32; j += 8)
        g_WinT[(size_t)(bx + y0 + j) * DD + by + x] = tile[x][y0 + j];
}

// ---------------- Cq precompute (one-time, fp32) ----------------
__global__ __launch_bounds__(256, 1) void cq_kernel(const float* __restrict__ context) {
    __shared__ float ws[32][128];
    __shared__ float xs[32][64];
    const int tid = threadIdx.x;
    const int rowBase = blockIdx.x * 128;
    const int s = blockIdx.y;
    const int rg4 = (tid >> 3) << 2, b8 = (tid & 7) << 3;
    const int wrow = tid & 127, wkh = tid >> 7;
    const int xb = tid & 63, xkg = tid >> 6;

    ull acc[4][4];
    #pragma unroll
    for (int r = 0; r < 4; r++)
        #pragma unroll
        for (int p = 0; p < 4; p++) acc[r][p] = 0ull;

    for (int k0 = 0; k0 < DD; k0 += 32) {
        {
            const float* src = g_WinT + (size_t)(rowBase + wrow) * DD + k0 + wkh * 16;
            #pragma unroll
            for (int i = 0; i < 16; i += 4) {
                float4 v = *(const float4*)(src + i);
                ws[wkh * 16 + i + 0][wrow] = v.x;
                ws[wkh * 16 + i + 1][wrow] = v.y;
                ws[wkh * 16 + i + 2][wrow] = v.z;
                ws[wkh * 16 + i + 3][wrow] = v.w;
            }
        }
        {
            const float* src = context + (size_t)(s * BB + xb) * DD + k0 + xkg * 8;
            float4 v0 = *(const float4*)(src);
            float4 v1 = *(const float4*)(src + 4);
            xs[xkg * 8 + 0][xb] = v0.x; xs[xkg * 8 + 1][xb] = v0.y;
            xs[xkg * 8 + 2][xb] = v0.z; xs[xkg * 8 + 3][xb] = v0.w;
            xs[xkg * 8 + 4][xb] = v1.x; xs[xkg * 8 + 5][xb] = v1.y;
            xs[xkg * 8 + 6][xb] = v1.z; xs[xkg * 8 + 7][xb] = v1.w;
        }
        __syncthreads();
        #pragma unroll 8
        for (int kk = 0; kk < 32; kk++) {
            float4 wv = *(const float4*)&ws[kk][rg4];
            ull w0 = dup2(wv.x), w1 = dup2(wv.y), w2 = dup2(wv.z), w3 = dup2(wv.w);
            ulonglong2 xa = *(const ulonglong2*)&xs[kk][b8];
            ulonglong2 xc = *(const ulonglong2*)&xs[kk][b8 + 4];
            ffma2(acc[0][0], w0, xa.x); ffma2(acc[0][1], w0, xa.y);
            ffma2(acc[0][2], w0, xc.x); ffma2(acc[0][3], w0, xc.y);
            ffma2(acc[1][0], w1, xa.x); ffma2(acc[1][1], w1, xa.y);
            ffma2(acc[1][2], w1, xc.x); ffma2(acc[1][3], w1, xc.y);
            ffma2(acc[2][0], w2, xa.x); ffma2(acc[2][1], w2, xa.y);
            ffma2(acc[2][2], w2, xc.x); ffma2(acc[2][3], w2, xc.y);
            ffma2(acc[3][0], w3, xa.x); ffma2(acc[3][1], w3, xa.y);
            ffma2(acc[3][2], w3, xc.x); ffma2(acc[3][3], w3, xc.y);
        }
        __syncthreads();
    }
    #pragma unroll
    for (int r = 0; r < 4; r++) {
        int krow = rowBase + rg4 + r;
        #pragma unroll
        for (int p = 0; p < 4; p++) {
            float2 v = *(float2*)&acc[r][p];
            g_Cq[(size_t)(s * BB + b8 + 2 * p) * DD + krow]     = v.x;
            g_Cq[(size_t)(s * BB + b8 + 2 * p + 1) * DD + krow] = v.y;
        }
    }
}

// ---------------- weight fragment pack (one-time) ----------------
// FIX vs rounds 7/8: destination selected by tag INSIDE device code.
// Passing g_Wf* from host passed the host shadow-symbol address; on GB300
// (ATS) those writes landed silently in host memory and the device arrays
// stayed zero.
__global__ void pack_kernel(const float* __restrict__ W1, int ld1, int off1,
                            const float* __restrict__ W2, int ld2, int K1w,
                            int K8tot, int mbTot, int which) {
    uint4* __restrict__ dst = (which == 0) ? g_WfE
                            : (which == 1) ? g_Wf0
                            : (which == 2) ? g_Wf1 : g_WfO;
    size_t idx = (size_t)blockIdx.x * 256 + threadIdx.x;
    size_t total = (size_t)mbTot * K8tot * 32;
    if (idx >= total) return;
    int lane = (int)(idx & 31);
    size_t f = idx >> 5;
    int k8 = (int)(f % K8tot);
    int mb = (int)(f / K8tot);
    int g = lane >> 2, t = lane & 3;
    int r0 = mb * 16 + g, r8 = r0 + 8;
    int c = k8 * 8 + t;
    float a0 = (c < K1w) ? W1[(size_t)r0 * ld1 + off1 + c] : W2[(size_t)r0 * ld2 + (c - K1w)];
    float a1 = (c < K1w) ? W1[(size_t)r8 * ld1 + off1 + c] : W2[(size_t)r8 * ld2 + (c - K1w)];
    int c4 = c + 4;
    float a2 = (c4 < K1w) ? W1[(size_t)r0 * ld1 + off1 + c4] : W2[(size_t)r0 * ld2 + (c4 - K1w)];
    float a3 = (c4 < K1w) ? W1[(size_t)r8 * ld1 + off1 + c4] : W2[(size_t)r8 * ld2 + (c4 - K1w)];
    dst[idx] = make_uint4(tf32c(a0), tf32c(a1), tf32c(a2), tf32c(a3));
}

// ---------------- pipelined tf32 GEMM core ----------------
__device__ __forceinline__ void issueA(SmemGemm* sm, const uint4* __restrict__ Wf,
                                       int K8tot, int mbG0, int k8Base,
                                       int chunk, int buf, int wid, int lane) {
    int k8c = k8Base + (chunk << 2);
    #pragma unroll
    for (int j = 0; j < 4; j++) {
        int mbk = j * 16 + wid;
        int mbL = mbk >> 2, k8L = mbk & 3;
        const uint4* src = Wf + ((size_t)(mbG0 + mbL) * K8tot + (k8c + k8L)) * 32 + lane;
        unsigned dst = (unsigned)__cvta_generic_to_shared(&sm->A[buf][mbL][k8L][lane]);
        asm volatile("cp.async.cg.shared.global [%0], [%1], 16;" :: "r"(dst), "l"(src));
    }
    asm volatile("cp.async.commit_group;" ::: "memory");
}

__device__ __forceinline__ void loadB(const float* const* rp1, const float* const* rp2,
                                      int KX1, int ksBase, int chunk,
                                      int wid, int g, int t4, float pbv[2][2]) {
    int k0 = ksBase + (chunk << 5);
    #pragma unroll
    for (int j = 0; j < 2; j++) {
        int nbk = j * 16 + wid;
        int nb = nbk >> 2, k8 = nbk & 3;
        int b = nb * 8 + g;
        int k = k0 + k8 * 8 + t4;
        const float* s = (k < KX1) ? rp1[b] + k : rp2[b] + (k - KX1);
        pbv[j][0] = s[0];
        pbv[j][1] = s[4];
    }
}

// CTA tile 256 rows x 64 batch, 16 warps (8m x 2n), warp tile 32x32.
__device__ __forceinline__ void gemm_async(
    int rowBase, int ksBase, int KS,
    const uint4* __restrict__ Wf, int K8tot,
    const float* const* rp1, const float* const* rp2, int KX1,
    float* __restrict__ partOut, SmemGemm* sm) {
    const int tid = threadIdx.x;
    const int wid = tid >> 5, lane = tid & 31;
    const int g = lane >> 2, t4 = lane & 3;
    const int mb0 = (wid >> 1) << 1;
    const int nb0 = (wid & 1) << 2;
    const int mbG0 = rowBase >> 4;
    const int k8Base = ksBase >> 3;
    const int nChunk = KS >> 5;

    float acc[2][4][4];
    #pragma unroll
    for (int i = 0; i < 2; i++)
        #pragma unroll
        for (int j = 0; j < 4; j++)
            #pragma unroll
            for (int r = 0; r < 4; r++) acc[i][j][r] = 0.f;

    issueA(sm, Wf, K8tot, mbG0, k8Base, 0, 0, wid, lane);
    if (nChunk > 1) issueA(sm, Wf, K8tot, mbG0, k8Base, 1, 1, wid, lane);
    float pb[2][2];
    loadB(rp1, rp2, KX1, ksBase, 0, wid, g, t4, pb);

    for (int i = 0; i < nChunk; i++) {
        #pragma unroll
        for (int j = 0; j < 2; j++) {
            int nbk = j * 16 + wid;
            int nb = nbk >> 2, k8 = nbk & 3;
            sm->Bf[i & 1][nb][k8][lane] = make_uint2(tf32c(pb[j][0]), tf32c(pb[j][1]));
        }
        float pbn[2][2];
        if (i + 1 < nChunk) {
            loadB(rp1, rp2, KX1, ksBase, i + 1, wid, g, t4, pbn);
            asm volatile("cp.async.wait_group 1;" ::: "memory");
        } else {
            asm volatile("cp.async.wait_group 0;" ::: "memory");
        }
        __syncthreads();
        const int ab = i % 3;
        #pragma unroll
        for (int k8 = 0; k8 < 4; k8++) {
            uint4 a0 = sm->A[ab][mb0][k8][lane];
            uint4 a1 = sm->A[ab][mb0 + 1][k8][lane];
            #pragma unroll
            for (int nj = 0; nj < 4; nj++) {
                uint2 bb = sm->Bf[i & 1][nb0 + nj][k8][lane];
                mma_tf32(acc[0][nj], (const unsigned*)&a0, (const unsigned*)&bb);
                mma_tf32(acc[1][nj], (const unsigned*)&a1, (const unsigned*)&bb);
            }
        }
        __syncthreads();   // all reads of A[ab]/Bf done before reuse
        if (i + 2 < nChunk)
            issueA(sm, Wf, K8tot, mbG0, k8Base, i + 2, (i + 2) % 3, wid, lane);
        if (i + 1 < nChunk) {
            pb[0][0] = pbn[0][0]; pb[0][1] = pbn[0][1];
            pb[1][0] = pbn[1][0]; pb[1][1] = pbn[1][1];
        }
    }

    #pragma unroll
    for (int mi = 0; mi < 2; mi++) {
        int rb = rowBase + (mb0 + mi) * 16 + g;
        #pragma unroll
        for (int nj = 0; nj < 4; nj++) {
            int col = (nb0 + nj) * 8 + 2 * t4;
            *(float2*)&partOut[(size_t)rb * 64 + col]       = make_float2(acc[mi][nj][0], acc[mi][nj][1]);
            *(float2*)&partOut[(size_t)(rb + 8) * 64 + col] = make_float2(acc[mi][nj][2], acc[mi][nj][3]);
        }
    }
}

// ---------------- emb projection (one-time, tensor cores) ----------------
__global__ __launch_bounds__(NTHR, 1) void pre_emb_kernel(
    const int* __restrict__ input, const float* __restrict__ word_lut) {
    extern __shared__ char dynsm[];
    SmemGemm* sm = (SmemGemm*)dynsm;
    __shared__ const float* rp1[64];
    __shared__ const float* rp2[64];
    const int t = blockIdx.y;
    if (threadIdx.x < 64) {
        int tok = input[threadIdx.x * TT + t];
        rp1[threadIdx.x] = word_lut + (size_t)tok * EE;
        rp2[threadIdx.x] = rp1[threadIdx.x];
    }
    __syncthreads();
    gemm_async(blockIdx.x * 256, 0, EE, g_WfE, EE / 8,
               rp1, rp2, 1 << 30, g_pre + (size_t)t * 4096 * 64, sm);
}

// ---------------- step phases ----------------
__device__ __forceinline__ void cell_phase(int layer, int t) {
    int e = blockIdx.x * NTHR + threadIdx.x;    // 65536 = BB*DD
    int b = e & 63, d = e >> 6;
    const float* bias = layer ? g_bias1 : g_bias0;
    float gg[4];
    #pragma unroll
    for (int gate = 0; gate < 4; gate++) {
        int row = gate * DD + d;
        float s = bias[row];
        if (layer == 0) s += g_pre[((size_t)t * 4096 + row) * 64 + b];
        #pragma unroll
        for (int ks = 0; ks < 8; ks++)
            s += g_part[((size_t)ks * 4096 + row) * 64 + b];
        gg[gate] = s;
    }
    if (layer) {
        float cn = sigm(gg[1]) * g_c1[b][d] + sigm(gg[0]) * tanhf(gg[2]);
        g_c1[b][d] = cn;
        g_h1[b][d] = sigm(gg[3]) * tanhf(cn);
    } else {
        float cn = sigm(gg[1]) * g_c0[b][d] + sigm(gg[0]) * tanhf(gg[2]);
        g_c0[b][d] = cn;
        g_h0[b][d] = sigm(gg[3]) * tanhf(cn);
    }
}

__device__ __forceinline__ void attn_phase(
    int t, const float* __restrict__ context, float* __restrict__ attns,
    SmemAttn* sm, float* sc, float* red) {
    const int tid = threadIdx.x;
    const int b = blockIdx.x >> 1;
    const int half = blockIdx.x & 1;
    const int lane = tid & 31, warp = tid >> 5;

    for (int i = tid; i < DD; i += NTHR) sm->h1s[i] = g_h1[b][i];
    __syncthreads();

    #pragma unroll
    for (int i = 0; i < 8; i++) {
        int s = warp + 16 * i;
        const float4* cp = (const float4*)(g_Cq + (size_t)(s * BB + b) * DD);
        float p = 0.f;
        #pragma unroll
        for (int j = 0; j < 8; j++) {
            int d4 = lane + j * 32;
            float4 v = cp[d4];
            p += v.x * sm->h1s[4 * d4] + v.y * sm->h1s[4 * d4 + 1] +
                 v.z * sm->h1s[4 * d4 + 2] + v.w * sm->h1s[4 * d4 + 3];
        }
        #pragma unroll
        for (int off = 16; off; off >>= 1) p += __shfl_xor_sync(~0u, p, off);
        if (lane == 0) sc[s] = p;
    }
    __syncthreads();

    float v = (tid < 128) ? sc[tid] : -1e30f;
    float m = v;
    #pragma unroll
    for (int off = 16; off; off >>= 1) m = fmaxf(m, __shfl_xor_sync(~0u, m, off));
    if (tid < 128 && lane == 0) red[warp] = m;
    __syncthreads();
    m = fmaxf(fmaxf(red[0], red[1]), fmaxf(red[2], red[3]));
    float ex = (tid < 128) ? __expf(v - m) : 0.f;
    float ssum = ex;
    #pragma unroll
    for (int off = 16; off; off >>= 1) ssum += __shfl_xor_sync(~0u, ssum, off);
    if (tid < 128 && lane == 0) red[4 + warp] = ssum;
    __syncthreads();
    ssum = red[4] + red[5] + red[6] + red[7];
    if (tid < 128) {
        float a = ex / ssum;
        sc[tid] = a;
        if (half == 0) attns[((size_t)b * TT + t) * SS + tid] = a;
    }
    __syncthreads();

    const int g = tid >> 7, j = tid & 127;
    const int d4 = half * 512 + j * 4;
    float4 a4 = make_float4(0.f, 0.f, 0.f, 0.f);
    #pragma unroll 4
    for (int s = g * 32; s < g * 32 + 32; s++) {
        float as = sc[s];
        float4 vv = *(const float4*)(context + (size_t)(s * BB + b) * DD + d4);
        a4.x += as * vv.x; a4.y += as * vv.y; a4.z += as * vv.z; a4.w += as * vv.w;
    }
    sm->wbuf[g][j] = a4;
    __syncthreads();
    if (g == 0) {
        float4 r0 = sm->wbuf[0][j], r1 = sm->wbuf[1][j], r2 = sm->wbuf[2][j], r3 = sm->wbuf[3][j];
        float4 o = make_float4(r0.x + r1.x + r2.x + r3.x, r0.y + r1.y + r2.y + r3.y,
                               r0.z + r1.z + r2.z + r3.z, r0.w + r1.w + r2.w + r3.w);
        *(float4*)&g_wctx[b][d4] = o;
    }
    __syncthreads();
}

__device__ __forceinline__ void outred_phase(int t, float* __restrict__ outs) {
    int e = blockIdx.x * NTHR + threadIdx.x;
    int b = e & 63, d = e >> 6;
    float s = 0.f;
    #pragma unroll
    for (int ks = 0; ks < 32; ks++)
        s += g_part[((size_t)ks * 1024 + d) * 64 + b];
    float v = tanhf(s);
    g_out[b][d] = v;
    outs[((size_t)b * TT + t) * DD + d] = v;
}

// ---------------- one timestep = one kernel (proven structure) ----------------
__global__ __launch_bounds__(NTHR, 1) void step_kernel(
    int t, const float* __restrict__ context,
    float* __restrict__ outs, float* __restrict__ attns) {
    extern __shared__ char dynsm[];
    SmemU* sm = (SmemU*)dynsm;
    __shared__ const float* rp1[64];
    __shared__ const float* rp2[64];
    __shared__ float sc[SS];
    __shared__ float red[8];
    const int tid = threadIdx.x;
    const int bid = blockIdx.x;

    // lstm0 gates: x = [out | h0], K=2048, 16 rowtiles x 8 ksplit
    if (tid < 64) { rp1[tid] = &g_out[tid][0]; rp2[tid] = &g_h0[tid][0]; }
    __syncthreads();
    gemm_async((bid & 15) * 256, (bid >> 4) * 256, 256, g_Wf0, 256,
               rp1, rp2, DD, g_part + (size_t)(bid >> 4) * 4096 * 64, &sm->g);
    grid_barrier();
    cell_phase(0, t);
    grid_barrier();
    // lstm1 gates: x = [h0 | h1]
    if (tid < 64) { rp1[tid] = &g_h0[tid][0]; rp2[tid] = &g_h1[tid][0]; }
    __syncthreads();
    gemm_async((bid & 15) * 256, (bid >> 4) * 256, 256, g_Wf1, 256,
               rp1, rp2, DD, g_part + (size_t)(bid >> 4) * 4096 * 64, &sm->g);
    grid_barrier();
    cell_phase(1, t);
    grid_barrier();
    attn_phase(t, context, attns, &sm->a, sc, red);
    grid_barrier();
    // out gemm: x = [wctx | h1], 4 rowtiles x 32 ksplit
    if (tid < 64) { rp1[tid] = &g_wctx[tid][0]; rp2[tid] = &g_h1[tid][0]; }
    __syncthreads();
    gemm_async((bid & 3) * 256, (bid >> 2) * 64, 64, g_WfO, 256,
               rp1, rp2, DD, g_part + (size_t)(bid >> 2) * 1024 * 64, &sm->g);
    grid_barrier();
    outred_phase(t, outs);
}

// ---------------- final ----------------
__global__ void final_kernel(float* __restrict__ hout, float* __restrict__ cout) {
    int i = blockIdx.x * blockDim.x + threadIdx.x;
    if (i < BB * DD) {
        hout[i]           = ((float*)g_h0)[i];
        hout[BB * DD + i] = ((float*)g_h1)[i];
        cout[i]           = ((float*)g_c0)[i];
        cout[BB * DD + i] = ((float*)g_c1)[i];
    }
}

// ---------------- launch ----------------
extern "C" void kernel_launch(void* const* d_in, const int* in_sizes, int n_in,
                              void* d_out, int out_size) {
    const int*   input    = (const int*)d_in[0];
    const float* h0       = (const float*)d_in[2];
    const float* c0       = (const float*)d_in[3];
    const float* context  = (const float*)d_in[4];
    const float* init_out = (const float*)d_in[5];
    const float* word_lut = (const float*)d_in[6];
    const float* Wih0 = (const float*)d_in[7];
    const float* Whh0 = (const float*)d_in[8];
    const float* bih0 = (const float*)d_in[9];
    const float* bhh0 = (const float*)d_in[10];
    const float* Wih1 = (const float*)d_in[11];
    const float* Whh1 = (const float*)d_in[12];
    const float* bih1 = (const float*)d_in[13];
    const float* bhh1 = (const float*)d_in[14];
    const float* Win  = (const float*)d_in[15];
    const float* Wout = (const float*)d_in[16];

    float* out   = (float*)d_out;
    float* outs  = out;                           // [B,T,D]
    float* hout  = out + (size_t)BB * TT * DD;    // [2,B,D]
    float* cout  = hout + 2 * BB * DD;            // [2,B,D]
    float* attns = cout + 2 * BB * DD;            // [B,T,S]

    cudaFuncSetAttribute(step_kernel, cudaFuncAttributeMaxDynamicSharedMemorySize,
                         (int)sizeof(SmemU));
    cudaFuncSetAttribute(pre_emb_kernel, cudaFuncAttributeMaxDynamicSharedMemorySize,
                         (int)sizeof(SmemGemm));

    init_kernel<<<256, 256>>>(h0, c0, init_out, bih0, bhh0, bih1, bhh1);
    transpose_kernel<<<dim3(32, 32), dim3(32, 8)>>>(Win);
    cq_kernel<<<dim3(8, 128), 256>>>(context);
    // packs: (W1, ld1, off1, W2, ld2, K1w, K8tot, mbTot, which)
    pack_kernel<<<2048, 256>>>(Wih0, 1536, 0,   Wih0, 1536, 512,  64,  256, 0);
    pack_kernel<<<8192, 256>>>(Wih0, 1536, 512, Whh0, 1024, 1024, 256, 256, 1);
    pack_kernel<<<8192, 256>>>(Wih1, 1024, 0,   Whh1, 1024, 1024, 256, 256, 2);
    pack_kernel<<<2048, 256>>>(Wout, 2048, 0,   Wout, 2048, 2048, 256, 64,  3);
    pre_emb_kernel<<<dim3(16, 128), NTHR, sizeof(SmemGemm)>>>(input, word_lut);
    for (int t = 0; t < TT; t++) {
        step_kernel<<<NCTA, NTHR, sizeof(SmemU)>>>(t, context, outs, attns);
    }
    final_kernel<<<256, 256>>>(hout, cout);
}

// round 10
// speedup vs baseline: 7.4604x; 1.0040x over previous
#include <cuda_runtime.h>
#include <math.h>

#define BB 64
#define DD 1024
#define TT 128
#define SS 128
#define EE 512
#define NCTA 128
#define NTHR 512

typedef unsigned long long ull;

// ---------------- device scratch (static, no allocations) ----------------
__device__ float g_h0[BB][DD];
__device__ float g_h1[BB][DD];
__device__ float g_c0[BB][DD];
__device__ float g_c1[BB][DD];
__device__ float g_out[BB][DD];
__device__ float g_wctx[BB][DD];
__device__ float g_bias0[4 * DD];
__device__ float g_bias1[4 * DD];
__device__ float g_WinT[DD * DD];
__device__ float g_Cq[(size_t)SS * BB * DD];            // ctx @ W_in : [s][b][k]
__device__ float g_part[8 * 4096 * 64];                 // split-K partials
__device__ float g_pre[(size_t)TT * 4096 * BB];         // emb projection [t][row][b]

// pre-packed tf32 fragment weights: idx = ((mb*K8 + k8)*32 + lane)
__device__ uint4 g_WfE[256 * 64 * 32];    // lstm0 emb part:  4096 x 512
__device__ uint4 g_Wf0[256 * 256 * 32];   // lstm0 [out|h0]:  4096 x 2048
__device__ uint4 g_Wf1[256 * 256 * 32];   // lstm1 [h0|h1]:   4096 x 2048
__device__ uint4 g_WfO[64 * 256 * 32];    // out  [wctx|h1]:  1024 x 2048

__device__ unsigned g_bar_count;
__device__ volatile unsigned g_bar_epoch;

__device__ __forceinline__ float sigm(float x) { return 1.f / (1.f + __expf(-x)); }

__device__ __forceinline__ void ffma2(ull &d, ull a, ull b) {
    asm("fma.rn.f32x2 %0, %1, %2, %0;" : "+l"(d) : "l"(a), "l"(b));
}
__device__ __forceinline__ ull dup2(float w) {
    ull r; asm("mov.b64 %0, {%1, %1};" : "=l"(r) : "f"(w)); return r;
}
__device__ __forceinline__ unsigned tf32c(float x) {
    unsigned r; asm("cvt.rna.tf32.f32 %0, %1;" : "=r"(r) : "f"(x)); return r;
}
__device__ __forceinline__ void mma_tf32(float* c, const unsigned* a, const unsigned* b) {
    asm volatile(
        "mma.sync.aligned.m16n8k8.row.col.f32.tf32.tf32.f32 "
        "{%0,%1,%2,%3}, {%4,%5,%6,%7}, {%8,%9}, {%0,%1,%2,%3};"
        : "+f"(c[0]), "+f"(c[1]), "+f"(c[2]), "+f"(c[3])
        : "r"(a[0]), "r"(a[1]), "r"(a[2]), "r"(a[3]), "r"(b[0]), "r"(b[1]));
}

// software grid barrier (128 CTAs, all resident)
__device__ __forceinline__ void grid_barrier() {
    __syncthreads();
    if (threadIdx.x == 0) {
        unsigned e = g_bar_epoch;
        __threadfence();
        unsigned a = atomicAdd(&g_bar_count, 1u);
        if (a == NCTA - 1) {
            g_bar_count = 0;
            __threadfence();
            atomicAdd((unsigned*)&g_bar_epoch, 1u);
        } else {
            while (g_bar_epoch == e) { __nanosleep(32); }
        }
        __threadfence();
    }
    __syncthreads();
}

// ---------------- shared-mem layouts ----------------
struct SmemGemm {
    uint4 A[3][16][4][32];   // 96KB  A frags, 3-stage
    uint2 Bf[2][8][4][32];   // 16KB  B frags, 2-stage
};
struct SmemAttn {
    float h1s[DD];
    float4 wbuf[4][128];
};
union SmemU {
    SmemGemm g;
    SmemAttn a;
};

// ---------------- init ----------------
__global__ void init_kernel(const float* __restrict__ h0, const float* __restrict__ c0,
                            const float* __restrict__ io,
                            const float* __restrict__ bih0, const float* __restrict__ bhh0,
                            const float* __restrict__ bih1, const float* __restrict__ bhh1) {
    int i = blockIdx.x * blockDim.x + threadIdx.x;
    if (i < BB * DD) {
        ((float*)g_h0)[i] = h0[i];
        ((float*)g_h1)[i] = h0[BB * DD + i];
        ((float*)g_c0)[i] = c0[i];
        ((float*)g_c1)[i] = c0[BB * DD + i];
        ((float*)g_out)[i] = io[i];
    }
    if (i < 4 * DD) {
        g_bias0[i] = bih0[i] + bhh0[i];
        g_bias1[i] = bih1[i] + bhh1[i];
    }
}

// ---------------- transpose W_in (for Cq) ----------------
__global__ void transpose_kernel(const float* __restrict__ Win) {
    __shared__ float tile[32][33];
    int bx = blockIdx.x * 32, by = blockIdx.y * 32;
    int x = threadIdx.x, y0 = threadIdx.y;
    #pragma unroll
    for (int j = 0; j < 32; j += 8)
        tile[y0 + j][x] = Win[(size_t)(by + y0 + j) * DD + bx + x];
    __syncthreads();
    #pragma unroll
    for (int j = 0; j < 32; j += 8)
        g_WinT[(size_t)(bx + y0 + j) * DD + by + x] = tile[x][y0 + j];
}

// ---------------- Cq precompute (one-time, fp32) ----------------
__global__ __launch_bounds__(256, 1) void cq_kernel(const float* __restrict__ context) {
    __shared__ float ws[32][128];
    __shared__ float xs[32][64];
    const int tid = threadIdx.x;
    const int rowBase = blockIdx.x * 128;
    const int s = blockIdx.y;
    const int rg4 = (tid >> 3) << 2, b8 = (tid & 7) << 3;
    const int wrow = tid & 127, wkh = tid >> 7;
    const int xb = tid & 63, xkg = tid >> 6;

    ull acc[4][4];
    #pragma unroll
    for (int r = 0; r < 4; r++)
        #pragma unroll
        for (int p = 0; p < 4; p++) acc[r][p] = 0ull;

    for (int k0 = 0; k0 < DD; k0 += 32) {
        {
            const float* src = g_WinT + (size_t)(rowBase + wrow) * DD + k0 + wkh * 16;
            #pragma unroll
            for (int i = 0; i < 16; i += 4) {
                float4 v = *(const float4*)(src + i);
                ws[wkh * 16 + i + 0][wrow] = v.x;
                ws[wkh * 16 + i + 1][wrow] = v.y;
                ws[wkh * 16 + i + 2][wrow] = v.z;
                ws[wkh * 16 + i + 3][wrow] = v.w;
            }
        }
        {
            const float* src = context + (size_t)(s * BB + xb) * DD + k0 + xkg * 8;
            float4 v0 = *(const float4*)(src);
            float4 v1 = *(const float4*)(src + 4);
            xs[xkg * 8 + 0][xb] = v0.x; xs[xkg * 8 + 1][xb] = v0.y;
            xs[xkg * 8 + 2][xb] = v0.z; xs[xkg * 8 + 3][xb] = v0.w;
            xs[xkg * 8 + 4][xb] = v1.x; xs[xkg * 8 + 5][xb] = v1.y;
            xs[xkg * 8 + 6][xb] = v1.z; xs[xkg * 8 + 7][xb] = v1.w;
        }
        __syncthreads();
        #pragma unroll 8
        for (int kk = 0; kk < 32; kk++) {
            float4 wv = *(const float4*)&ws[kk][rg4];
            ull w0 = dup2(wv.x), w1 = dup2(wv.y), w2 = dup2(wv.z), w3 = dup2(wv.w);
            ulonglong2 xa = *(const ulonglong2*)&xs[kk][b8];
            ulonglong2 xc = *(const ulonglong2*)&xs[kk][b8 + 4];
            ffma2(acc[0][0], w0, xa.x); ffma2(acc[0][1], w0, xa.y);
            ffma2(acc[0][2], w0, xc.x); ffma2(acc[0][3], w0, xc.y);
            ffma2(acc[1][0], w1, xa.x); ffma2(acc[1][1], w1, xa.y);
            ffma2(acc[1][2], w1, xc.x); ffma2(acc[1][3], w1, xc.y);
            ffma2(acc[2][0], w2, xa.x); ffma2(acc[2][1], w2, xa.y);
            ffma2(acc[2][2], w2, xc.x); ffma2(acc[2][3], w2, xc.y);
            ffma2(acc[3][0], w3, xa.x); ffma2(acc[3][1], w3, xa.y);
            ffma2(acc[3][2], w3, xc.x); ffma2(acc[3][3], w3, xc.y);
        }
        __syncthreads();
    }
    #pragma unroll
    for (int r = 0; r < 4; r++) {
        int krow = rowBase + rg4 + r;
        #pragma unroll
        for (int p = 0; p < 4; p++) {
            float2 v = *(float2*)&acc[r][p];
            g_Cq[(size_t)(s * BB + b8 + 2 * p) * DD + krow]     = v.x;
            g_Cq[(size_t)(s * BB + b8 + 2 * p + 1) * DD + krow] = v.y;
        }
    }
}

// ---------------- weight fragment pack (one-time) ----------------
// Destination selected by tag INSIDE device code (host passing of __device__
// symbols silently writes host memory on GB300/ATS — rounds 7/8 bug).
__global__ void pack_kernel(const float* __restrict__ W1, int ld1, int off1,
                            const float* __restrict__ W2, int ld2, int K1w,
                            int K8tot, int mbTot, int which) {
    uint4* __restrict__ dst = (which == 0) ? g_WfE
                            : (which == 1) ? g_Wf0
                            : (which == 2) ? g_Wf1 : g_WfO;
    size_t idx = (size_t)blockIdx.x * 256 + threadIdx.x;
    size_t total = (size_t)mbTot * K8tot * 32;
    if (idx >= total) return;
    int lane = (int)(idx & 31);
    size_t f = idx >> 5;
    int k8 = (int)(f % K8tot);
    int mb = (int)(f / K8tot);
    int g = lane >> 2, t = lane & 3;
    int r0 = mb * 16 + g, r8 = r0 + 8;
    int c = k8 * 8 + t;
    float a0 = (c < K1w) ? W1[(size_t)r0 * ld1 + off1 + c] : W2[(size_t)r0 * ld2 + (c - K1w)];
    float a1 = (c < K1w) ? W1[(size_t)r8 * ld1 + off1 + c] : W2[(size_t)r8 * ld2 + (c - K1w)];
    int c4 = c + 4;
    float a2 = (c4 < K1w) ? W1[(size_t)r0 * ld1 + off1 + c4] : W2[(size_t)r0 * ld2 + (c4 - K1w)];
    float a3 = (c4 < K1w) ? W1[(size_t)r8 * ld1 + off1 + c4] : W2[(size_t)r8 * ld2 + (c4 - K1w)];
    dst[idx] = make_uint4(tf32c(a0), tf32c(a1), tf32c(a2), tf32c(a3));
}

// ---------------- pipelined tf32 GEMM core ----------------
__device__ __forceinline__ void issueA(SmemGemm* sm, const uint4* __restrict__ Wf,
                                       int K8tot, int mbG0, int k8Base,
                                       int chunk, int buf, int wid, int lane) {
    int k8c = k8Base + (chunk << 2);
    #pragma unroll
    for (int j = 0; j < 4; j++) {
        int mbk = j * 16 + wid;
        int mbL = mbk >> 2, k8L = mbk & 3;
        const uint4* src = Wf + ((size_t)(mbG0 + mbL) * K8tot + (k8c + k8L)) * 32 + lane;
        unsigned dst = (unsigned)__cvta_generic_to_shared(&sm->A[buf][mbL][k8L][lane]);
        asm volatile("cp.async.cg.shared.global [%0], [%1], 16;" :: "r"(dst), "l"(src));
    }
    asm volatile("cp.async.commit_group;" ::: "memory");
}

__device__ __forceinline__ void loadB(const float* const* rp1, const float* const* rp2,
                                      int KX1, int ksBase, int chunk,
                                      int wid, int g, int t4, float pbv[2][2]) {
    int k0 = ksBase + (chunk << 5);
    #pragma unroll
    for (int j = 0; j < 2; j++) {
        int nbk = j * 16 + wid;
        int nb = nbk >> 2, k8 = nbk & 3;
        int b = nb * 8 + g;
        int k = k0 + k8 * 8 + t4;
        const float* s = (k < KX1) ? rp1[b] + k : rp2[b] + (k - KX1);
        pbv[j][0] = s[0];
        pbv[j][1] = s[4];
    }
}

// CTA tile 256 rows x 64 batch, 16 warps (8m x 2n), warp tile 32x32.
__device__ __forceinline__ void gemm_async(
    int rowBase, int ksBase, int KS,
    const uint4* __restrict__ Wf, int K8tot,
    const float* const* rp1, const float* const* rp2, int KX1,
    float* __restrict__ partOut, SmemGemm* sm) {
    const int tid = threadIdx.x;
    const int wid = tid >> 5, lane = tid & 31;
    const int g = lane >> 2, t4 = lane & 3;
    const int mb0 = (wid >> 1) << 1;
    const int nb0 = (wid & 1) << 2;
    const int mbG0 = rowBase >> 4;
    const int k8Base = ksBase >> 3;
    const int nChunk = KS >> 5;

    float acc[2][4][4];
    #pragma unroll
    for (int i = 0; i < 2; i++)
        #pragma unroll
        for (int j = 0; j < 4; j++)
            #pragma unroll
            for (int r = 0; r < 4; r++) acc[i][j][r] = 0.f;

    issueA(sm, Wf, K8tot, mbG0, k8Base, 0, 0, wid, lane);
    if (nChunk > 1) issueA(sm, Wf, K8tot, mbG0, k8Base, 1, 1, wid, lane);
    float pb[2][2];
    loadB(rp1, rp2, KX1, ksBase, 0, wid, g, t4, pb);

    for (int i = 0; i < nChunk; i++) {
        #pragma unroll
        for (int j = 0; j < 2; j++) {
            int nbk = j * 16 + wid;
            int nb = nbk >> 2, k8 = nbk & 3;
            sm->Bf[i & 1][nb][k8][lane] = make_uint2(tf32c(pb[j][0]), tf32c(pb[j][1]));
        }
        float pbn[2][2];
        if (i + 1 < nChunk) {
            loadB(rp1, rp2, KX1, ksBase, i + 1, wid, g, t4, pbn);
            asm volatile("cp.async.wait_group 1;" ::: "memory");
        } else {
            asm volatile("cp.async.wait_group 0;" ::: "memory");
        }
        __syncthreads();
        const int ab = i % 3;
        #pragma unroll
        for (int k8 = 0; k8 < 4; k8++) {
            uint4 a0 = sm->A[ab][mb0][k8][lane];
            uint4 a1 = sm->A[ab][mb0 + 1][k8][lane];
            #pragma unroll
            for (int nj = 0; nj < 4; nj++) {
                uint2 bb = sm->Bf[i & 1][nb0 + nj][k8][lane];
                mma_tf32(acc[0][nj], (const unsigned*)&a0, (const unsigned*)&bb);
                mma_tf32(acc[1][nj], (const unsigned*)&a1, (const unsigned*)&bb);
            }
        }
        // no second syncthreads: A[ (i+2)%3 ] and Bf[(i+1)&1] never overlap
        // buffers still being read this iteration; the top-of-iteration sync
        // orders the next same-buffer write against these reads.
        if (i + 2 < nChunk)
            issueA(sm, Wf, K8tot, mbG0, k8Base, i + 2, (i + 2) % 3, wid, lane);
        if (i + 1 < nChunk) {
            pb[0][0] = pbn[0][0]; pb[0][1] = pbn[0][1];
            pb[1][0] = pbn[1][0]; pb[1][1] = pbn[1][1];
        }
    }
    __syncthreads();   // protect smem reuse by the next phase

    #pragma unroll
    for (int mi = 0; mi < 2; mi++) {
        int rb = rowBase + (mb0 + mi) * 16 + g;
        #pragma unroll
        for (int nj = 0; nj < 4; nj++) {
            int col = (nb0 + nj) * 8 + 2 * t4;
            *(float2*)&partOut[(size_t)rb * 64 + col]       = make_float2(acc[mi][nj][0], acc[mi][nj][1]);
            *(float2*)&partOut[(size_t)(rb + 8) * 64 + col] = make_float2(acc[mi][nj][2], acc[mi][nj][3]);
        }
    }
}

// ---------------- emb projection (one-time, tensor cores) ----------------
__global__ __launch_bounds__(NTHR, 1) void pre_emb_kernel(
    const int* __restrict__ input, const float* __restrict__ word_lut) {
    extern __shared__ char dynsm[];
    SmemGemm* sm = (SmemGemm*)dynsm;
    __shared__ const float* rp1[64];
    __shared__ const float* rp2[64];
    const int t = blockIdx.y;
    if (threadIdx.x < 64) {
        int tok = input[threadIdx.x * TT + t];
        rp1[threadIdx.x] = word_lut + (size_t)tok * EE;
        rp2[threadIdx.x] = rp1[threadIdx.x];
    }
    __syncthreads();
    gemm_async(blockIdx.x * 256, 0, EE, g_WfE, EE / 8,
               rp1, rp2, 1 << 30, g_pre + (size_t)t * 4096 * 64, sm);
}

// ---------------- step phases ----------------
__device__ __forceinline__ void cell_phase(int layer, int t) {
    int e = blockIdx.x * NTHR + threadIdx.x;    // 65536 = BB*DD
    int b = e & 63, d = e >> 6;
    const float* bias = layer ? g_bias1 : g_bias0;
    float gg[4];
    #pragma unroll
    for (int gate = 0; gate < 4; gate++) {
        int row = gate * DD + d;
        float s = bias[row];
        if (layer == 0) s += g_pre[((size_t)t * 4096 + row) * 64 + b];
        #pragma unroll
        for (int ks = 0; ks < 8; ks++)
            s += g_part[((size_t)ks * 4096 + row) * 64 + b];
        gg[gate] = s;
    }
    if (layer) {
        float cn = sigm(gg[1]) * g_c1[b][d] + sigm(gg[0]) * tanhf(gg[2]);
        g_c1[b][d] = cn;
        g_h1[b][d] = sigm(gg[3]) * tanhf(cn);
    } else {
        float cn = sigm(gg[1]) * g_c0[b][d] + sigm(gg[0]) * tanhf(gg[2]);
        g_c0[b][d] = cn;
        g_h0[b][d] = sigm(gg[3]) * tanhf(cn);
    }
}

__device__ __forceinline__ void attn_phase(
    int t, const float* __restrict__ context, float* __restrict__ attns,
    SmemAttn* sm, float* sc, float* red) {
    const int tid = threadIdx.x;
    const int b = blockIdx.x >> 1;
    const int half = blockIdx.x & 1;
    const int lane = tid & 31, warp = tid >> 5;

    for (int i = tid; i < DD; i += NTHR) sm->h1s[i] = g_h1[b][i];
    __syncthreads();

    #pragma unroll
    for (int i = 0; i < 8; i++) {
        int s = warp + 16 * i;
        const float4* cp = (const float4*)(g_Cq + (size_t)(s * BB + b) * DD);
        float p = 0.f;
        #pragma unroll
        for (int j = 0; j < 8; j++) {
            int d4 = lane + j * 32;
            float4 v = cp[d4];
            p += v.x * sm->h1s[4 * d4] + v.y * sm->h1s[4 * d4 + 1] +
                 v.z * sm->h1s[4 * d4 + 2] + v.w * sm->h1s[4 * d4 + 3];
        }
        #pragma unroll
        for (int off = 16; off; off >>= 1) p += __shfl_xor_sync(~0u, p, off);
        if (lane == 0) sc[s] = p;
    }
    __syncthreads();

    float v = (tid < 128) ? sc[tid] : -1e30f;
    float m = v;
    #pragma unroll
    for (int off = 16; off; off >>= 1) m = fmaxf(m, __shfl_xor_sync(~0u, m, off));
    if (tid < 128 && lane == 0) red[warp] = m;
    __syncthreads();
    m = fmaxf(fmaxf(red[0], red[1]), fmaxf(red[2], red[3]));
    float ex = (tid < 128) ? __expf(v - m) : 0.f;
    float ssum = ex;
    #pragma unroll
    for (int off = 16; off; off >>= 1) ssum += __shfl_xor_sync(~0u, ssum, off);
    if (tid < 128 && lane == 0) red[4 + warp] = ssum;
    __syncthreads();
    ssum = red[4] + red[5] + red[6] + red[7];
    if (tid < 128) {
        float a = ex / ssum;
        sc[tid] = a;
        if (half == 0) attns[((size_t)b * TT + t) * SS + tid] = a;
    }
    __syncthreads();

    const int g = tid >> 7, j = tid & 127;
    const int d4 = half * 512 + j * 4;
    float4 a4 = make_float4(0.f, 0.f, 0.f, 0.f);
    #pragma unroll 4
    for (int s = g * 32; s < g * 32 + 32; s++) {
        float as = sc[s];
        float4 vv = *(const float4*)(context + (size_t)(s * BB + b) * DD + d4);
        a4.x += as * vv.x; a4.y += as * vv.y; a4.z += as * vv.z; a4.w += as * vv.w;
    }
    sm->wbuf[g][j] = a4;
    __syncthreads();
    if (g == 0) {
        float4 r0 = sm->wbuf[0][j], r1 = sm->wbuf[1][j], r2 = sm->wbuf[2][j], r3 = sm->wbuf[3][j];
        float4 o = make_float4(r0.x + r1.x + r2.x + r3.x, r0.y + r1.y + r2.y + r3.y,
                               r0.z + r1.z + r2.z + r3.z, r0.w + r1.w + r2.w + r3.w);
        *(float4*)&g_wctx[b][d4] = o;
    }
    __syncthreads();
}

__device__ __forceinline__ void outred_phase(int t, float* __restrict__ outs) {
    int e = blockIdx.x * NTHR + threadIdx.x;
    int b = e & 63, d = e >> 6;
    float s = 0.f;
    #pragma unroll
    for (int ks = 0; ks < 32; ks++)
        s += g_part[((size_t)ks * 1024 + d) * 64 + b];
    float v = tanhf(s);
    g_out[b][d] = v;
    outs[((size_t)b * TT + t) * DD + d] = v;
}

// ---------------- persistent kernel: all 128 timesteps ----------------
__global__ __launch_bounds__(NTHR, 1) void main_kernel(
    const float* __restrict__ context,
    float* __restrict__ outs, float* __restrict__ attns) {
    extern __shared__ char dynsm[];
    SmemU* sm = (SmemU*)dynsm;
    __shared__ const float* rp1[64];
    __shared__ const float* rp2[64];
    __shared__ float sc[SS];
    __shared__ float red[8];
    const int tid = threadIdx.x;
    const int bid = blockIdx.x;

    for (int t = 0; t < TT; t++) {
        // lstm0 gates: x = [out | h0], K=2048, 16 rowtiles x 8 ksplit
        if (tid < 64) { rp1[tid] = &g_out[tid][0]; rp2[tid] = &g_h0[tid][0]; }
        __syncthreads();
        gemm_async((bid & 15) * 256, (bid >> 4) * 256, 256, g_Wf0, 256,
                   rp1, rp2, DD, g_part + (size_t)(bid >> 4) * 4096 * 64, &sm->g);
        grid_barrier();
        cell_phase(0, t);
        grid_barrier();
        // lstm1 gates: x = [h0 | h1]
        if (tid < 64) { rp1[tid] = &g_h0[tid][0]; rp2[tid] = &g_h1[tid][0]; }
        __syncthreads();
        gemm_async((bid & 15) * 256, (bid >> 4) * 256, 256, g_Wf1, 256,
                   rp1, rp2, DD, g_part + (size_t)(bid >> 4) * 4096 * 64, &sm->g);
        grid_barrier();
        cell_phase(1, t);
        grid_barrier();
        attn_phase(t, context, attns, &sm->a, sc, red);
        grid_barrier();
        // out gemm: x = [wctx | h1], 4 rowtiles x 32 ksplit
        if (tid < 64) { rp1[tid] = &g_wctx[tid][0]; rp2[tid] = &g_h1[tid][0]; }
        __syncthreads();
        gemm_async((bid & 3) * 256, (bid >> 2) * 64, 64, g_WfO, 256,
                   rp1, rp2, DD, g_part + (size_t)(bid >> 2) * 1024 * 64, &sm->g);
        grid_barrier();
        outred_phase(t, outs);
        grid_barrier();     // next step's lstm0 reads g_out
    }
}

// ---------------- final ----------------
__global__ void final_kernel(float* __restrict__ hout, float* __restrict__ cout) {
    int i = blockIdx.x * blockDim.x + threadIdx.x;
    if (i < BB * DD) {
        hout[i]           = ((float*)g_h0)[i];
        hout[BB * DD + i] = ((float*)g_h1)[i];
        cout[i]           = ((float*)g_c0)[i];
        cout[BB * DD + i] = ((float*)g_c1)[i];
    }
}

// ---------------- launch ----------------
extern "C" void kernel_launch(void* const* d_in, const int* in_sizes, int n_in,
                              void* d_out, int out_size) {
    const int*   input    = (const int*)d_in[0];
    const float* h0       = (const float*)d_in[2];
    const float* c0       = (const float*)d_in[3];
    const float* context  = (const float*)d_in[4];
    const float* init_out = (const float*)d_in[5];
    const float* word_lut = (const float*)d_in[6];
    const float* Wih0 = (const float*)d_in[7];
    const float* Whh0 = (const float*)d_in[8];
    const float* bih0 = (const float*)d_in[9];
    const float* bhh0 = (const float*)d_in[10];
    const float* Wih1 = (const float*)d_in[11];
    const float* Whh1 = (const float*)d_in[12];
    const float* bih1 = (const float*)d_in[13];
    const float* bhh1 = (const float*)d_in[14];
    const float* Win  = (const float*)d_in[15];
    const float* Wout = (const float*)d_in[16];

    float* out   = (float*)d_out;
    float* outs  = out;                           // [B,T,D]
    float* hout  = out + (size_t)BB * TT * DD;    // [2,B,D]
    float* cout  = hout + 2 * BB * DD;            // [2,B,D]
    float* attns = cout + 2 * BB * DD;            // [B,T,S]

    cudaFuncSetAttribute(main_kernel, cudaFuncAttributeMaxDynamicSharedMemorySize,
                         (int)sizeof(SmemU));
    cudaFuncSetAttribute(pre_emb_kernel, cudaFuncAttributeMaxDynamicSharedMemorySize,
                         (int)sizeof(SmemGemm));

    init_kernel<<<256, 256>>>(h0, c0, init_out, bih0, bhh0, bih1, bhh1);
    transpose_kernel<<<dim3(32, 32), dim3(32, 8)>>>(Win);
    cq_kernel<<<dim3(8, 128), 256>>>(context);
    // packs: (W1, ld1, off1, W2, ld2, K1w, K8tot, mbTot, which)
    pack_kernel<<<2048, 256>>>(Wih0, 1536, 0,   Wih0, 1536, 512,  64,  256, 0);
    pack_kernel<<<8192, 256>>>(Wih0, 1536, 512, Whh0, 1024, 1024, 256, 256, 1);
    pack_kernel<<<8192, 256>>>(Wih1, 1024, 0,   Whh1, 1024, 1024, 256, 256, 2);
    pack_kernel<<<2048, 256>>>(Wout, 2048, 0,   Wout, 2048, 2048, 256, 64,  3);
    pre_emb_kernel<<<dim3(16, 128), NTHR, sizeof(SmemGemm)>>>(input, word_lut);
    main_kernel<<<NCTA, NTHR, sizeof(SmemU)>>>(context, outs, attns);
    final_kernel<<<256, 256>>>(hout, cout);
}

// round 11
// speedup vs baseline: 10.6136x; 1.4227x over previous
#include <cuda_runtime.h>
#include <cuda_fp16.h>
#include <math.h>

#define BB 64
#define DD 1024
#define TT 128
#define SS 128
#define EE 512
#define NCTA 128
#define NTHR 512

typedef unsigned long long ull;

// ---------------- device scratch (static, no allocations) ----------------
__device__ float g_h0[BB][DD];
__device__ float g_h1[BB][DD];
__device__ float g_c0[BB][DD];
__device__ float g_c1[BB][DD];
__device__ float g_out[BB][DD];
__device__ float g_wctx[BB][DD];
__device__ float g_bias0[4 * DD];
__device__ float g_bias1[4 * DD];
__device__ float g_WinT[DD * DD];
__device__ __half g_Cq16[(size_t)SS * BB * DD];         // (ctx @ W_in) fp16 : [s][b][k]
__device__ __half g_ctx16[(size_t)SS * BB * DD];        // context fp16 copy
__device__ float g_part[8 * 4096 * 64];                 // split-K partials
__device__ float g_pre[(size_t)TT * 4096 * BB];         // emb projection [t][row][b]

// pre-packed fp16 m16n8k16 fragment weights: idx = ((mb*K16 + k16)*32 + lane)
__device__ uint4 g_WfE[256 * 32 * 32];    // lstm0 emb part:  4096 x 512   (4.2MB)
__device__ uint4 g_Wf0[256 * 128 * 32];   // lstm0 [out|h0]:  4096 x 2048  (16.8MB)
__device__ uint4 g_Wf1[256 * 128 * 32];   // lstm1 [h0|h1]:   4096 x 2048  (16.8MB)
__device__ uint4 g_WfO[64 * 128 * 32];    // out  [wctx|h1]:  1024 x 2048  (4.2MB)

__device__ unsigned g_bar_count;
__device__ volatile unsigned g_bar_epoch;

__device__ __forceinline__ float sigm(float x) { return 1.f / (1.f + __expf(-x)); }

__device__ __forceinline__ void ffma2(ull &d, ull a, ull b) {
    asm("fma.rn.f32x2 %0, %1, %2, %0;" : "+l"(d) : "l"(a), "l"(b));
}
__device__ __forceinline__ ull dup2(float w) {
    ull r; asm("mov.b64 %0, {%1, %1};" : "=l"(r) : "f"(w)); return r;
}
__device__ __forceinline__ unsigned h2u(__half2 h) {
    return *(unsigned*)&h;
}
__device__ __forceinline__ void mma_f16(float* c, const unsigned* a, const unsigned* b) {
    asm volatile(
        "mma.sync.aligned.m16n8k16.row.col.f32.f16.f16.f32 "
        "{%0,%1,%2,%3}, {%4,%5,%6,%7}, {%8,%9}, {%0,%1,%2,%3};"
        : "+f"(c[0]), "+f"(c[1]), "+f"(c[2]), "+f"(c[3])
        : "r"(a[0]), "r"(a[1]), "r"(a[2]), "r"(a[3]), "r"(b[0]), "r"(b[1]));
}

// software grid barrier (128 CTAs, all resident)
__device__ __forceinline__ void grid_barrier() {
    __syncthreads();
    if (threadIdx.x == 0) {
        unsigned e = g_bar_epoch;
        __threadfence();
        unsigned a = atomicAdd(&g_bar_count, 1u);
        if (a == NCTA - 1) {
            g_bar_count = 0;
            __threadfence();
            atomicAdd((unsigned*)&g_bar_epoch, 1u);
        } else {
            while (g_bar_epoch == e) { __nanosleep(32); }
        }
        __threadfence();
    }
    __syncthreads();
}

// ---------------- shared-mem layouts ----------------
struct SmemGemm {
    uint4 A[3][16][2][32];   // 48KB  A fp16 frags, 3-stage
    uint2 Bf[2][8][2][32];   // 8KB   B fp16 frags, 2-stage
};
struct SmemAttn {
    float h1s[DD];           // 4KB
    float wbuf[8][64][8];    // 16KB
};
union SmemU {
    SmemGemm g;
    SmemAttn a;
};

// ---------------- init ----------------
__global__ void init_kernel(const float* __restrict__ h0, const float* __restrict__ c0,
                            const float* __restrict__ io,
                            const float* __restrict__ bih0, const float* __restrict__ bhh0,
                            const float* __restrict__ bih1, const float* __restrict__ bhh1) {
    int i = blockIdx.x * blockDim.x + threadIdx.x;
    if (i < BB * DD) {
        ((float*)g_h0)[i] = h0[i];
        ((float*)g_h1)[i] = h0[BB * DD + i];
        ((float*)g_c0)[i] = c0[i];
        ((float*)g_c1)[i] = c0[BB * DD + i];
        ((float*)g_out)[i] = io[i];
    }
    if (i < 4 * DD) {
        g_bias0[i] = bih0[i] + bhh0[i];
        g_bias1[i] = bih1[i] + bhh1[i];
    }
}

// ---------------- transpose W_in (for Cq) ----------------
__global__ void transpose_kernel(const float* __restrict__ Win) {
    __shared__ float tile[32][33];
    int bx = blockIdx.x * 32, by = blockIdx.y * 32;
    int x = threadIdx.x, y0 = threadIdx.y;
    #pragma unroll
    for (int j = 0; j < 32; j += 8)
        tile[y0 + j][x] = Win[(size_t)(by + y0 + j) * DD + bx + x];
    __syncthreads();
    #pragma unroll
    for (int j = 0; j < 32; j += 8)
        g_WinT[(size_t)(bx + y0 + j) * DD + by + x] = tile[x][y0 + j];
}

// ---------------- context -> fp16 copy (one-time) ----------------
__global__ void ctx16_kernel(const float* __restrict__ context) {
    size_t i = (size_t)blockIdx.x * 256 + threadIdx.x;
    if (i < (size_t)SS * BB * DD) g_ctx16[i] = __float2half(context[i]);
}

// ---------------- Cq precompute (one-time, fp32 math, fp16 store) ----------------
__global__ __launch_bounds__(256, 1) void cq_kernel(const float* __restrict__ context) {
    __shared__ float ws[32][128];
    __shared__ float xs[32][64];
    const int tid = threadIdx.x;
    const int rowBase = blockIdx.x * 128;
    const int s = blockIdx.y;
    const int rg4 = (tid >> 3) << 2, b8 = (tid & 7) << 3;
    const int wrow = tid & 127, wkh = tid >> 7;
    const int xb = tid & 63, xkg = tid >> 6;

    ull acc[4][4];
    #pragma unroll
    for (int r = 0; r < 4; r++)
        #pragma unroll
        for (int p = 0; p < 4; p++) acc[r][p] = 0ull;

    for (int k0 = 0; k0 < DD; k0 += 32) {
        {
            const float* src = g_WinT + (size_t)(rowBase + wrow) * DD + k0 + wkh * 16;
            #pragma unroll
            for (int i = 0; i < 16; i += 4) {
                float4 v = *(const float4*)(src + i);
                ws[wkh * 16 + i + 0][wrow] = v.x;
                ws[wkh * 16 + i + 1][wrow] = v.y;
                ws[wkh * 16 + i + 2][wrow] = v.z;
                ws[wkh * 16 + i + 3][wrow] = v.w;
            }
        }
        {
            const float* src = context + (size_t)(s * BB + xb) * DD + k0 + xkg * 8;
            float4 v0 = *(const float4*)(src);
            float4 v1 = *(const float4*)(src + 4);
            xs[xkg * 8 + 0][xb] = v0.x; xs[xkg * 8 + 1][xb] = v0.y;
            xs[xkg * 8 + 2][xb] = v0.z; xs[xkg * 8 + 3][xb] = v0.w;
            xs[xkg * 8 + 4][xb] = v1.x; xs[xkg * 8 + 5][xb] = v1.y;
            xs[xkg * 8 + 6][xb] = v1.z; xs[xkg * 8 + 7][xb] = v1.w;
        }
        __syncthreads();
        #pragma unroll 8
        for (int kk = 0; kk < 32; kk++) {
            float4 wv = *(const float4*)&ws[kk][rg4];
            ull w0 = dup2(wv.x), w1 = dup2(wv.y), w2 = dup2(wv.z), w3 = dup2(wv.w);
            ulonglong2 xa = *(const ulonglong2*)&xs[kk][b8];
            ulonglong2 xc = *(const ulonglong2*)&xs[kk][b8 + 4];
            ffma2(acc[0][0], w0, xa.x); ffma2(acc[0][1], w0, xa.y);
            ffma2(acc[0][2], w0, xc.x); ffma2(acc[0][3], w0, xc.y);
            ffma2(acc[1][0], w1, xa.x); ffma2(acc[1][1], w1, xa.y);
            ffma2(acc[1][2], w1, xc.x); ffma2(acc[1][3], w1, xc.y);
            ffma2(acc[2][0], w2, xa.x); ffma2(acc[2][1], w2, xa.y);
            ffma2(acc[2][2], w2, xc.x); ffma2(acc[2][3], w2, xc.y);
            ffma2(acc[3][0], w3, xa.x); ffma2(acc[3][1], w3, xa.y);
            ffma2(acc[3][2], w3, xc.x); ffma2(acc[3][3], w3, xc.y);
        }
        __syncthreads();
    }
    #pragma unroll
    for (int r = 0; r < 4; r++) {
        int krow = rowBase + rg4 + r;
        #pragma unroll
        for (int p = 0; p < 4; p++) {
            float2 v = *(float2*)&acc[r][p];
            g_Cq16[(size_t)(s * BB + b8 + 2 * p) * DD + krow]     = __float2half(v.x);
            g_Cq16[(size_t)(s * BB + b8 + 2 * p + 1) * DD + krow] = __float2half(v.y);
        }
    }
}

// ---------------- weight fragment pack (one-time, fp16 m16n8k16 layout) ------
// Destination selected by tag INSIDE device code (host passing of __device__
// symbols silently writes host memory on GB300/ATS — rounds 7/8 bug).
__global__ void pack_kernel(const float* __restrict__ W1, int ld1, int off1,
                            const float* __restrict__ W2, int ld2, int K1w,
                            int K16tot, int mbTot, int which) {
    uint4* __restrict__ dst = (which == 0) ? g_WfE
                            : (which == 1) ? g_Wf0
                            : (which == 2) ? g_Wf1 : g_WfO;
    size_t idx = (size_t)blockIdx.x * 256 + threadIdx.x;
    size_t total = (size_t)mbTot * K16tot * 32;
    if (idx >= total) return;
    int lane = (int)(idx & 31);
    size_t f = idx >> 5;
    int k16 = (int)(f % K16tot);
    int mb = (int)(f / K16tot);
    int g = lane >> 2, t = lane & 3;
    int r0 = mb * 16 + g, r8 = r0 + 8;
    int cA = k16 * 16 + 2 * t;   // cols cA, cA+1
    int cB = cA + 8;             // cols cB, cB+1
    // K1w is a multiple of 16 everywhere -> pairs never straddle W1/W2.
    #define LDW(r, c) (((c) < K1w) ? W1[(size_t)(r) * ld1 + off1 + (c)] \
                                   : W2[(size_t)(r) * ld2 + ((c) - K1w)])
    __half2 h0 = __floats2half2_rn(LDW(r0, cA), LDW(r0, cA + 1));
    __half2 h1 = __floats2half2_rn(LDW(r8, cA), LDW(r8, cA + 1));
    __half2 h2 = __floats2half2_rn(LDW(r0, cB), LDW(r0, cB + 1));
    __half2 h3 = __floats2half2_rn(LDW(r8, cB), LDW(r8, cB + 1));
    #undef LDW
    dst[idx] = make_uint4(h2u(h0), h2u(h1), h2u(h2), h2u(h3));
}

// ---------------- pipelined fp16 GEMM core ----------------
__device__ __forceinline__ void issueA(SmemGemm* sm, const uint4* __restrict__ Wf,
                                       int K16tot, int mbG0, int k16Base,
                                       int chunk, int buf, int wid, int lane) {
    int k16c = k16Base + (chunk << 1);
    #pragma unroll
    for (int j = 0; j < 2; j++) {
        int mbk = j * 16 + wid;             // 0..31
        int mbL = mbk >> 1, k16L = mbk & 1;
        const uint4* src = Wf + ((size_t)(mbG0 + mbL) * K16tot + (k16c + k16L)) * 32 + lane;
        unsigned dst = (unsigned)__cvta_generic_to_shared(&sm->A[buf][mbL][k16L][lane]);
        asm volatile("cp.async.cg.shared.global [%0], [%1], 16;" :: "r"(dst), "l"(src));
    }
    asm volatile("cp.async.commit_group;" ::: "memory");
}

__device__ __forceinline__ void loadB(const float* const* rp1, const float* const* rp2,
                                      int KX1, int ksBase, int chunk,
                                      int wid, int g, int t4, float pbv[4]) {
    int k0 = ksBase + (chunk << 5);
    int nb = wid >> 1, k16 = wid & 1;
    int b = nb * 8 + g;
    int kbase = k0 + k16 * 16;
    const float* s = (kbase < KX1) ? rp1[b] + kbase : rp2[b] + (kbase - KX1);
    float2 v0 = *(const float2*)(s + 2 * t4);
    float2 v1 = *(const float2*)(s + 2 * t4 + 8);
    pbv[0] = v0.x; pbv[1] = v0.y; pbv[2] = v1.x; pbv[3] = v1.y;
}

// CTA tile 256 rows x 64 batch, 16 warps (8m x 2n), warp tile 32x32, fp16 MMA.
__device__ __forceinline__ void gemm_async(
    int rowBase, int ksBase, int KS,
    const uint4* __restrict__ Wf, int K16tot,
    const float* const* rp1, const float* const* rp2, int KX1,
    float* __restrict__ partOut, SmemGemm* sm) {
    const int tid = threadIdx.x;
    const int wid = tid >> 5, lane = tid & 31;
    const int g = lane >> 2, t4 = lane & 3;
    const int mb0 = (wid >> 1) << 1;
    const int nb0 = (wid & 1) << 2;
    const int mbG0 = rowBase >> 4;
    const int k16Base = ksBase >> 4;
    const int nChunk = KS >> 5;
    const int nbS = wid >> 1, k16S = wid & 1;   // B staging slot for this thread

    float acc[2][4][4];
    #pragma unroll
    for (int i = 0; i < 2; i++)
        #pragma unroll
        for (int j = 0; j < 4; j++)
            #pragma unroll
            for (int r = 0; r < 4; r++) acc[i][j][r] = 0.f;

    issueA(sm, Wf, K16tot, mbG0, k16Base, 0, 0, wid, lane);
    if (nChunk > 1) issueA(sm, Wf, K16tot, mbG0, k16Base, 1, 1, wid, lane);
    float pb[4];
    loadB(rp1, rp2, KX1, ksBase, 0, wid, g, t4, pb);

    for (int i = 0; i < nChunk; i++) {
        {
            __half2 hA = __floats2half2_rn(pb[0], pb[1]);
            __half2 hB = __floats2half2_rn(pb[2], pb[3]);
            sm->Bf[i & 1][nbS][k16S][lane] = make_uint2(h2u(hA), h2u(hB));
        }
        float pbn[4];
        if (i + 1 < nChunk) {
            loadB(rp1, rp2, KX1, ksBase, i + 1, wid, g, t4, pbn);
            asm volatile("cp.async.wait_group 1;" ::: "memory");
        } else {
            asm volatile("cp.async.wait_group 0;" ::: "memory");
        }
        __syncthreads();
        const int ab = i % 3;
        #pragma unroll
        for (int k16 = 0; k16 < 2; k16++) {
            uint4 a0 = sm->A[ab][mb0][k16][lane];
            uint4 a1 = sm->A[ab][mb0 + 1][k16][lane];
            #pragma unroll
            for (int nj = 0; nj < 4; nj++) {
                uint2 bb = sm->Bf[i & 1][nb0 + nj][k16][lane];
                mma_f16(acc[0][nj], (const unsigned*)&a0, (const unsigned*)&bb);
                mma_f16(acc[1][nj], (const unsigned*)&a1, (const unsigned*)&bb);
            }
        }
        if (i + 2 < nChunk)
            issueA(sm, Wf, K16tot, mbG0, k16Base, i + 2, (i + 2) % 3, wid, lane);
        if (i + 1 < nChunk) {
            pb[0] = pbn[0]; pb[1] = pbn[1]; pb[2] = pbn[2]; pb[3] = pbn[3];
        }
    }
    __syncthreads();   // protect smem reuse by the next phase

    #pragma unroll
    for (int mi = 0; mi < 2; mi++) {
        int rb = rowBase + (mb0 + mi) * 16 + g;
        #pragma unroll
        for (int nj = 0; nj < 4; nj++) {
            int col = (nb0 + nj) * 8 + 2 * t4;
            *(float2*)&partOut[(size_t)rb * 64 + col]       = make_float2(acc[mi][nj][0], acc[mi][nj][1]);
            *(float2*)&partOut[(size_t)(rb + 8) * 64 + col] = make_float2(acc[mi][nj][2], acc[mi][nj][3]);
        }
    }
}

// ---------------- emb projection (one-time, tensor cores) ----------------
__global__ __launch_bounds__(NTHR, 1) void pre_emb_kernel(
    const int* __restrict__ input, const float* __restrict__ word_lut) {
    extern __shared__ char dynsm[];
    SmemGemm* sm = (SmemGemm*)dynsm;
    __shared__ const float* rp1[64];
    __shared__ const float* rp2[64];
    const int t = blockIdx.y;
    if (threadIdx.x < 64) {
        int tok = input[threadIdx.x * TT + t];
        rp1[threadIdx.x] = word_lut + (size_t)tok * EE;
        rp2[threadIdx.x] = rp1[threadIdx.x];
    }
    __syncthreads();
    gemm_async(blockIdx.x * 256, 0, EE, g_WfE, EE / 16,
               rp1, rp2, 1 << 30, g_pre + (size_t)t * 4096 * 64, sm);
}

// ---------------- step phases ----------------
__device__ __forceinline__ void cell_phase(int layer, int t) {
    int e = blockIdx.x * NTHR + threadIdx.x;    // 65536 = BB*DD
    int b = e & 63, d = e >> 6;
    const float* bias = layer ? g_bias1 : g_bias0;
    float gg[4];
    #pragma unroll
    for (int gate = 0; gate < 4; gate++) {
        int row = gate * DD + d;
        float s = bias[row];
        if (layer == 0) s += g_pre[((size_t)t * 4096 + row) * 64 + b];
        #pragma unroll
        for (int ks = 0; ks < 8; ks++)
            s += g_part[((size_t)ks * 4096 + row) * 64 + b];
        gg[gate] = s;
    }
    if (layer) {
        float cn = sigm(gg[1]) * g_c1[b][d] + sigm(gg[0]) * tanhf(gg[2]);
        g_c1[b][d] = cn;
        g_h1[b][d] = sigm(gg[3]) * tanhf(cn);
    } else {
        float cn = sigm(gg[1]) * g_c0[b][d] + sigm(gg[0]) * tanhf(gg[2]);
        g_c0[b][d] = cn;
        g_h0[b][d] = sigm(gg[3]) * tanhf(cn);
    }
}

__device__ __forceinline__ void attn_phase(
    int t, float* __restrict__ attns,
    SmemAttn* sm, float* sc, float* red) {
    const int tid = threadIdx.x;
    const int b = blockIdx.x >> 1;
    const int half = blockIdx.x & 1;
    const int lane = tid & 31, warp = tid >> 5;

    for (int i = tid; i < DD; i += NTHR) sm->h1s[i] = g_h1[b][i];
    __syncthreads();

    // scores[s] = Cq16[s,b,:] . h1
    #pragma unroll
    for (int i = 0; i < 8; i++) {
        int s = warp + 16 * i;
        const uint4* cp = (const uint4*)(g_Cq16 + (size_t)(s * BB + b) * DD);
        float p = 0.f;
        #pragma unroll
        for (int jj = 0; jj < 4; jj++) {
            int u = lane + jj * 32;
            uint4 q = cp[u];
            const __half2* hh = (const __half2*)&q;
            float2 f0 = __half22float2(hh[0]);
            float2 f1 = __half22float2(hh[1]);
            float2 f2 = __half22float2(hh[2]);
            float2 f3 = __half22float2(hh[3]);
            int base = u * 8;
            p += f0.x * sm->h1s[base]     + f0.y * sm->h1s[base + 1] +
                 f1.x * sm->h1s[base + 2] + f1.y * sm->h1s[base + 3] +
                 f2.x * sm->h1s[base + 4] + f2.y * sm->h1s[base + 5] +
                 f3.x * sm->h1s[base + 6] + f3.y * sm->h1s[base + 7];
        }
        #pragma unroll
        for (int off = 16; off; off >>= 1) p += __shfl_xor_sync(~0u, p, off);
        if (lane == 0) sc[s] = p;
    }
    __syncthreads();

    float v = (tid < 128) ? sc[tid] : -1e30f;
    float m = v;
    #pragma unroll
    for (int off = 16; off; off >>= 1) m = fmaxf(m, __shfl_xor_sync(~0u, m, off));
    if (tid < 128 && lane == 0) red[warp] = m;
    __syncthreads();
    m = fmaxf(fmaxf(red[0], red[1]), fmaxf(red[2], red[3]));
    float ex = (tid < 128) ? __expf(v - m) : 0.f;
    float ssum = ex;
    #pragma unroll
    for (int off = 16; off; off >>= 1) ssum += __shfl_xor_sync(~0u, ssum, off);
    if (tid < 128 && lane == 0) red[4 + warp] = ssum;
    __syncthreads();
    ssum = red[4] + red[5] + red[6] + red[7];
    if (tid < 128) {
        float a = ex / ssum;
        sc[tid] = a;
        if (half == 0) attns[((size_t)b * TT + t) * SS + tid] = a;
    }
    __syncthreads();

    // wctx[d] = sum_s a[s] * ctx16[s,b,d]; 8 s-groups x 64 d8-columns
    const int g8 = tid >> 6, j = tid & 63;
    const int d8 = half * 512 + j * 8;
    float a8[8];
    #pragma unroll
    for (int q = 0; q < 8; q++) a8[q] = 0.f;
    for (int s = g8 * 16; s < g8 * 16 + 16; s++) {
        float as = sc[s];
        uint4 vv = *(const uint4*)(g_ctx16 + (size_t)(s * BB + b) * DD + d8);
        const __half2* hh = (const __half2*)&vv;
        float2 f0 = __half22float2(hh[0]);
        float2 f1 = __half22float2(hh[1]);
        float2 f2 = __half22float2(hh[2]);
        float2 f3 = __half22float2(hh[3]);
        a8[0] += as * f0.x; a8[1] += as * f0.y;
        a8[2] += as * f1.x; a8[3] += as * f1.y;
        a8[4] += as * f2.x; a8[5] += as * f2.y;
        a8[6] += as * f3.x; a8[7] += as * f3.y;
    }
    #pragma unroll
    for (int q = 0; q < 8; q++) sm->wbuf[g8][j][q] = a8[q];
    __syncthreads();
    if (g8 == 0) {
        float o[8];
        #pragma unroll
        for (int q = 0; q < 8; q++) o[q] = 0.f;
        #pragma unroll
        for (int gg = 0; gg < 8; gg++)
            #pragma unroll
            for (int q = 0; q < 8; q++) o[q] += sm->wbuf[gg][j][q];
        *(float4*)&g_wctx[b][d8]     = make_float4(o[0], o[1], o[2], o[3]);
        *(float4*)&g_wctx[b][d8 + 4] = make_float4(o[4], o[5], o[6], o[7]);
    }
    __syncthreads();
}

__device__ __forceinline__ void outred_phase(int t, float* __restrict__ outs) {
    int e = blockIdx.x * NTHR + threadIdx.x;
    int b = e & 63, d = e >> 6;
    float s = 0.f;
    #pragma unroll
    for (int ks = 0; ks < 32; ks++)
        s += g_part[((size_t)ks * 1024 + d) * 64 + b];
    float v = tanhf(s);
    g_out[b][d] = v;
    outs[((size_t)b * TT + t) * DD + d] = v;
}

// ---------------- persistent kernel: all 128 timesteps ----------------
__global__ __launch_bounds__(NTHR, 1) void main_kernel(
    float* __restrict__ outs, float* __restrict__ attns) {
    extern __shared__ char dynsm[];
    SmemU* sm = (SmemU*)dynsm;
    __shared__ const float* rp1[64];
    __shared__ const float* rp2[64];
    __shared__ float sc[SS];
    __shared__ float red[8];
    const int tid = threadIdx.x;
    const int bid = blockIdx.x;

    for (int t = 0; t < TT; t++) {
        // lstm0 gates: x = [out | h0], K=2048, 16 rowtiles x 8 ksplit
        if (tid < 64) { rp1[tid] = &g_out[tid][0]; rp2[tid] = &g_h0[tid][0]; }
        __syncthreads();
        gemm_async((bid & 15) * 256, (bid >> 4) * 256, 256, g_Wf0, 128,
                   rp1, rp2, DD, g_part + (size_t)(bid >> 4) * 4096 * 64, &sm->g);
        grid_barrier();
        cell_phase(0, t);
        grid_barrier();
        // lstm1 gates: x = [h0 | h1]
        if (tid < 64) { rp1[tid] = &g_h0[tid][0]; rp2[tid] = &g_h1[tid][0]; }
        __syncthreads();
        gemm_async((bid & 15) * 256, (bid >> 4) * 256, 256, g_Wf1, 128,
                   rp1, rp2, DD, g_part + (size_t)(bid >> 4) * 4096 * 64, &sm->g);
        grid_barrier();
        cell_phase(1, t);
        grid_barrier();
        attn_phase(t, attns, &sm->a, sc, red);
        grid_barrier();
        // out gemm: x = [wctx | h1], 4 rowtiles x 32 ksplit
        if (tid < 64) { rp1[tid] = &g_wctx[tid][0]; rp2[tid] = &g_h1[tid][0]; }
        __syncthreads();
        gemm_async((bid & 3) * 256, (bid >> 2) * 64, 64, g_WfO, 128,
                   rp1, rp2, DD, g_part + (size_t)(bid >> 2) * 1024 * 64, &sm->g);
        grid_barrier();
        outred_phase(t, outs);
        grid_barrier();     // next step's lstm0 reads g_out
    }
}

// ---------------- final ----------------
__global__ void final_kernel(float* __restrict__ hout, float* __restrict__ cout) {
    int i = blockIdx.x * blockDim.x + threadIdx.x;
    if (i < BB * DD) {
        hout[i]           = ((float*)g_h0)[i];
        hout[BB * DD + i] = ((float*)g_h1)[i];
        cout[i]           = ((float*)g_c0)[i];
        cout[BB * DD + i] = ((float*)g_c1)[i];
    }
}

// ---------------- launch ----------------
extern "C" void kernel_launch(void* const* d_in, const int* in_sizes, int n_in,
                              void* d_out, int out_size) {
    const int*   input    = (const int*)d_in[0];
    const float* h0       = (const float*)d_in[2];
    const float* c0       = (const float*)d_in[3];
    const float* context  = (const float*)d_in[4];
    const float* init_out = (const float*)d_in[5];
    const float* word_lut = (const float*)d_in[6];
    const float* Wih0 = (const float*)d_in[7];
    const float* Whh0 = (const float*)d_in[8];
    const float* bih0 = (const float*)d_in[9];
    const float* bhh0 = (const float*)d_in[10];
    const float* Wih1 = (const float*)d_in[11];
    const float* Whh1 = (const float*)d_in[12];
    const float* bih1 = (const float*)d_in[13];
    const float* bhh1 = (const float*)d_in[14];
    const float* Win  = (const float*)d_in[15];
    const float* Wout = (const float*)d_in[16];

    float* out   = (float*)d_out;
    float* outs  = out;                           // [B,T,D]
    float* hout  = out + (size_t)BB * TT * DD;    // [2,B,D]
    float* cout  = hout + 2 * BB * DD;            // [2,B,D]
    float* attns = cout + 2 * BB * DD;            // [B,T,S]

    cudaFuncSetAttribute(main_kernel, cudaFuncAttributeMaxDynamicSharedMemorySize,
                         (int)sizeof(SmemU));
    cudaFuncSetAttribute(pre_emb_kernel, cudaFuncAttributeMaxDynamicSharedMemorySize,
                         (int)sizeof(SmemGemm));

    init_kernel<<<256, 256>>>(h0, c0, init_out, bih0, bhh0, bih1, bhh1);
    transpose_kernel<<<dim3(32, 32), dim3(32, 8)>>>(Win);
    ctx16_kernel<<<32768, 256>>>(context);
    cq_kernel<<<dim3(8, 128), 256>>>(context);
    // packs: (W1, ld1, off1, W2, ld2, K1w, K16tot, mbTot, which)
    pack_kernel<<<1024, 256>>>(Wih0, 1536, 0,   Wih0, 1536, 512,  32,  256, 0);
    pack_kernel<<<4096, 256>>>(Wih0, 1536, 512, Whh0, 1024, 1024, 128, 256, 1);
    pack_kernel<<<4096, 256>>>(Wih1, 1024, 0,   Whh1, 1024, 1024, 128, 256, 2);
    pack_kernel<<<1024, 256>>>(Wout, 2048, 0,   Wout, 2048, 2048, 128, 64,  3);
    pre_emb_kernel<<<dim3(16, 128), NTHR, sizeof(SmemGemm)>>>(input, word_lut);
    main_kernel<<<NCTA, NTHR, sizeof(SmemU)>>>(outs, attns);
    final_kernel<<<256, 256>>>(hout, cout);
}

// round 13
// speedup vs baseline: 11.7503x; 1.1071x over previous
#include <cuda_runtime.h>
#include <cuda_fp16.h>
#include <math.h>

#define BB 64
#define DD 1024
#define TT 128
#define SS 128
#define EE 512
#define NCTA 128
#define NTHR 512

typedef unsigned long long ull;

// ---------------- device scratch (static, no allocations) ----------------
__device__ float g_h0[BB][DD];
__device__ float g_h1[BB][DD];
__device__ float g_c0[BB][DD];
__device__ float g_c1[BB][DD];
__device__ float g_out[BB][DD];
__device__ float g_wctx[BB][DD];
__device__ float g_bias0[4 * DD];
__device__ float g_bias1[4 * DD];
__device__ __half g_Cq16[(size_t)SS * BB * DD];         // (ctx @ W_in) fp16 : [s][b][k]
__device__ __half g_ctx16[(size_t)SS * BB * DD];        // context fp16 copy
__device__ float g_part[8 * 4096 * 64];                 // split-K partials
__device__ float g_pre[(size_t)TT * 4096 * BB];         // emb projection [t][row][b]

// pre-packed fp16 m16n8k16 fragment weights: idx = ((mb*K16 + k16)*32 + lane)
__device__ uint4 g_WfE[256 * 32 * 32];    // lstm0 emb part:  4096 x 512
__device__ uint4 g_Wf0[256 * 128 * 32];   // lstm0 [out|h0]:  4096 x 2048
__device__ uint4 g_Wf1[256 * 128 * 32];   // lstm1 [h0|h1]:   4096 x 2048
__device__ uint4 g_WfO[64 * 128 * 32];    // out  [wctx|h1]:  1024 x 2048
__device__ uint4 g_WfQ[64 * 64 * 32];     // W_in^T:          1024 x 1024

__device__ unsigned g_bar_count;
__device__ volatile unsigned g_bar_epoch;

__device__ __forceinline__ float sigm(float x) { return 1.f / (1.f + __expf(-x)); }

__device__ __forceinline__ unsigned h2u(__half2 h) {
    return *(unsigned*)&h;
}
__device__ __forceinline__ void mma_f16(float* c, const unsigned* a, const unsigned* b) {
    asm volatile(
        "mma.sync.aligned.m16n8k16.row.col.f32.f16.f16.f32 "
        "{%0,%1,%2,%3}, {%4,%5,%6,%7}, {%8,%9}, {%0,%1,%2,%3};"
        : "+f"(c[0]), "+f"(c[1]), "+f"(c[2]), "+f"(c[3])
        : "r"(a[0]), "r"(a[1]), "r"(a[2]), "r"(a[3]), "r"(b[0]), "r"(b[1]));
}

// software grid barrier (128 CTAs, all resident)
__device__ __forceinline__ void grid_barrier() {
    __syncthreads();
    if (threadIdx.x == 0) {
        unsigned e = g_bar_epoch;
        __threadfence();
        unsigned a = atomicAdd(&g_bar_count, 1u);
        if (a == NCTA - 1) {
            g_bar_count = 0;
            __threadfence();
            atomicAdd((unsigned*)&g_bar_epoch, 1u);
        } else {
            while (g_bar_epoch == e) { }
        }
        __threadfence();
    }
    __syncthreads();
}

// ---------------- shared-mem layouts ----------------
struct SmemGemm {
    uint4 A[3][16][2][32];   // 48KB  A fp16 frags, 3-stage
    uint2 Bf[2][8][2][32];   // 8KB   B fp16 frags, 2-stage
};
struct SmemAttn {
    float h1s[DD];           // 4KB
    float wbuf[8][64][8];    // 16KB
};
union SmemU {
    SmemGemm g;
    SmemAttn a;
};

// ---------------- init ----------------
__global__ void init_kernel(const float* __restrict__ h0, const float* __restrict__ c0,
                            const float* __restrict__ io,
                            const float* __restrict__ bih0, const float* __restrict__ bhh0,
                            const float* __restrict__ bih1, const float* __restrict__ bhh1) {
    int i = blockIdx.x * blockDim.x + threadIdx.x;
    if (i < BB * DD) {
        ((float*)g_h0)[i] = h0[i];
        ((float*)g_h1)[i] = h0[BB * DD + i];
        ((float*)g_c0)[i] = c0[i];
        ((float*)g_c1)[i] = c0[BB * DD + i];
        ((float*)g_out)[i] = io[i];
    }
    if (i < 4 * DD) {
        g_bias0[i] = bih0[i] + bhh0[i];
        g_bias1[i] = bih1[i] + bhh1[i];
    }
}

// ---------------- context -> fp16 copy (one-time) ----------------
__global__ void ctx16_kernel(const float* __restrict__ context) {
    size_t i = (size_t)blockIdx.x * 256 + threadIdx.x;
    if (i < (size_t)SS * BB * DD) g_ctx16[i] = __float2half(context[i]);
}

// ---------------- weight fragment pack (one-time, fp16 m16n8k16 layout) ------
// Destination selected by tag INSIDE device code (host passing of __device__
// symbols silently writes host memory on GB300/ATS — rounds 7/8 bug).
// trans != 0: element (row r, contraction c) is read as W1[c*ld1 + r]
// (used for W_in: Cq needs A[k][d] = Win[d][k], i.e. Win transposed).
__global__ void pack_kernel(const float* __restrict__ W1, int ld1, int off1,
                            const float* __restrict__ W2, int ld2, int K1w,
                            int K16tot, int mbTot, int which, int trans) {
    uint4* __restrict__ dst = (which == 0) ? g_WfE
                            : (which == 1) ? g_Wf0
                            : (which == 2) ? g_Wf1
                            : (which == 3) ? g_WfO : g_WfQ;
    size_t idx = (size_t)blockIdx.x * 256 + threadIdx.x;
    size_t total = (size_t)mbTot * K16tot * 32;
    if (idx >= total) return;
    int lane = (int)(idx & 31);
    size_t f = idx >> 5;
    int k16 = (int)(f % K16tot);
    int mb = (int)(f / K16tot);
    int g = lane >> 2, t = lane & 3;
    int r0 = mb * 16 + g, r8 = r0 + 8;
    int cA = k16 * 16 + 2 * t;   // cols cA, cA+1
    int cB = cA + 8;             // cols cB, cB+1
    // K1w is a multiple of 16 everywhere -> pairs never straddle W1/W2.
    #define LDW(r, c) (trans ? W1[(size_t)(c) * ld1 + (r)] \
                     : ((c) < K1w) ? W1[(size_t)(r) * ld1 + off1 + (c)] \
                                   : W2[(size_t)(r) * ld2 + ((c) - K1w)])
    __half2 h0 = __floats2half2_rn(LDW(r0, cA), LDW(r0, cA + 1));
    __half2 h1 = __floats2half2_rn(LDW(r8, cA), LDW(r8, cA + 1));
    __half2 h2 = __floats2half2_rn(LDW(r0, cB), LDW(r0, cB + 1));
    __half2 h3 = __floats2half2_rn(LDW(r8, cB), LDW(r8, cB + 1));
    #undef LDW
    dst[idx] = make_uint4(h2u(h0), h2u(h1), h2u(h2), h2u(h3));
}

// ---------------- pipelined fp16 GEMM core ----------------
__device__ __forceinline__ void issueA(SmemGemm* sm, const uint4* __restrict__ Wf,
                                       int K16tot, int mbG0, int k16Base,
                                       int chunk, int buf, int wid, int lane) {
    int k16c = k16Base + (chunk << 1);
    #pragma unroll
    for (int j = 0; j < 2; j++) {
        int mbk = j * 16 + wid;             // 0..31
        int mbL = mbk >> 1, k16L = mbk & 1;
        const uint4* src = Wf + ((size_t)(mbG0 + mbL) * K16tot + (k16c + k16L)) * 32 + lane;
        unsigned dst = (unsigned)__cvta_generic_to_shared(&sm->A[buf][mbL][k16L][lane]);
        asm volatile("cp.async.cg.shared.global [%0], [%1], 16;" :: "r"(dst), "l"(src));
    }
    asm volatile("cp.async.commit_group;" ::: "memory");
}

__device__ __forceinline__ void loadB(const float* const* rp1, const float* const* rp2,
                                      int KX1, int ksBase, int chunk,
                                      int wid, int g, int t4, float pbv[4]) {
    int k0 = ksBase + (chunk << 5);
    int nb = wid >> 1, k16 = wid & 1;
    int b = nb * 8 + g;
    int kbase = k0 + k16 * 16;
    const float* s = (kbase < KX1) ? rp1[b] + kbase : rp2[b] + (kbase - KX1);
    float2 v0 = *(const float2*)(s + 2 * t4);
    float2 v1 = *(const float2*)(s + 2 * t4 + 8);
    pbv[0] = v0.x; pbv[1] = v0.y; pbv[2] = v1.x; pbv[3] = v1.y;
}

// CTA tile 256 rows x 64 batch, 16 warps (8m x 2n), warp tile 32x32, fp16 MMA.
// epi == 0: write fp32 partials partOut[row*64+b].
// epi == 1: write fp16 Cq at g_Cq16[(sIdx*BB+b)*DD + row].
__device__ __forceinline__ void gemm_async(
    int rowBase, int ksBase, int KS,
    const uint4* __restrict__ Wf, int K16tot,
    const float* const* rp1, const float* const* rp2, int KX1,
    float* __restrict__ partOut, SmemGemm* sm, int epi, int sIdx) {
    const int tid = threadIdx.x;
    const int wid = tid >> 5, lane = tid & 31;
    const int g = lane >> 2, t4 = lane & 3;
    const int mb0 = (wid >> 1) << 1;
    const int nb0 = (wid & 1) << 2;
    const int mbG0 = rowBase >> 4;
    const int k16Base = ksBase >> 4;
    const int nChunk = KS >> 5;
    const int nbS = wid >> 1, k16S = wid & 1;   // B staging slot for this thread

    float acc[2][4][4];
    #pragma unroll
    for (int i = 0; i < 2; i++)
        #pragma unroll
        for (int j = 0; j < 4; j++)
            #pragma unroll
            for (int r = 0; r < 4; r++) acc[i][j][r] = 0.f;

    issueA(sm, Wf, K16tot, mbG0, k16Base, 0, 0, wid, lane);
    if (nChunk > 1) issueA(sm, Wf, K16tot, mbG0, k16Base, 1, 1, wid, lane);
    float pb[4];
    loadB(rp1, rp2, KX1, ksBase, 0, wid, g, t4, pb);

    for (int i = 0; i < nChunk; i++) {
        {
            __half2 hA = __floats2half2_rn(pb[0], pb[1]);
            __half2 hB = __floats2half2_rn(pb[2], pb[3]);
            sm->Bf[i & 1][nbS][k16S][lane] = make_uint2(h2u(hA), h2u(hB));
        }
        float pbn[4];
        if (i + 1 < nChunk) {
            loadB(rp1, rp2, KX1, ksBase, i + 1, wid, g, t4, pbn);
            asm volatile("cp.async.wait_group 1;" ::: "memory");
        } else {
            asm volatile("cp.async.wait_group 0;" ::: "memory");
        }
        __syncthreads();
        const int ab = i % 3;
        #pragma unroll
        for (int k16 = 0; k16 < 2; k16++) {
            uint4 a0 = sm->A[ab][mb0][k16][lane];
            uint4 a1 = sm->A[ab][mb0 + 1][k16][lane];
            #pragma unroll
            for (int nj = 0; nj < 4; nj++) {
                uint2 bb = sm->Bf[i & 1][nb0 + nj][k16][lane];
                mma_f16(acc[0][nj], (const unsigned*)&a0, (const unsigned*)&bb);
                mma_f16(acc[1][nj], (const unsigned*)&a1, (const unsigned*)&bb);
            }
        }
        if (i + 2 < nChunk)
            issueA(sm, Wf, K16tot, mbG0, k16Base, i + 2, (i + 2) % 3, wid, lane);
        if (i + 1 < nChunk) {
            pb[0] = pbn[0]; pb[1] = pbn[1]; pb[2] = pbn[2]; pb[3] = pbn[3];
        }
    }
    __syncthreads();   // protect smem reuse by the next phase

    if (epi == 0) {
        #pragma unroll
        for (int mi = 0; mi < 2; mi++) {
            int rb = rowBase + (mb0 + mi) * 16 + g;
            #pragma unroll
            for (int nj = 0; nj < 4; nj++) {
                int col = (nb0 + nj) * 8 + 2 * t4;
                *(float2*)&partOut[(size_t)rb * 64 + col]       = make_float2(acc[mi][nj][0], acc[mi][nj][1]);
                *(float2*)&partOut[(size_t)(rb + 8) * 64 + col] = make_float2(acc[mi][nj][2], acc[mi][nj][3]);
            }
        }
    } else {
        // Cq epilogue: row = k index, col = batch
        #pragma unroll
        for (int mi = 0; mi < 2; mi++) {
            int rb = rowBase + (mb0 + mi) * 16 + g;
            #pragma unroll
            for (int nj = 0; nj < 4; nj++) {
                int col = (nb0 + nj) * 8 + 2 * t4;
                g_Cq16[((size_t)sIdx * BB + col)     * DD + rb]     = __float2half(acc[mi][nj][0]);
                g_Cq16[((size_t)sIdx * BB + col + 1) * DD + rb]     = __float2half(acc[mi][nj][1]);
                g_Cq16[((size_t)sIdx * BB + col)     * DD + rb + 8] = __float2half(acc[mi][nj][2]);
                g_Cq16[((size_t)sIdx * BB + col + 1) * DD + rb + 8] = __float2half(acc[mi][nj][3]);
            }
        }
    }
}

// ---------------- Cq precompute (one-time, tensor cores) ----------------
// Cq[s][b][k] = sum_d context[s][b][d] * Win[d][k]   (WfQ holds Win^T)
__global__ __launch_bounds__(NTHR, 1) void cq16_kernel(const float* __restrict__ context) {
    extern __shared__ char dynsm[];
    SmemGemm* sm = (SmemGemm*)dynsm;
    __shared__ const float* rp1[64];
    const int s = blockIdx.y;
    if (threadIdx.x < 64)
        rp1[threadIdx.x] = context + (size_t)(s * BB + threadIdx.x) * DD;
    __syncthreads();
    gemm_async(blockIdx.x * 256, 0, DD, g_WfQ, 64,
               rp1, rp1, 1 << 30, nullptr, sm, 1, s);
}

// ---------------- emb projection (one-time, tensor cores) ----------------
__global__ __launch_bounds__(NTHR, 1) void pre_emb_kernel(
    const int* __restrict__ input, const float* __restrict__ word_lut) {
    extern __shared__ char dynsm[];
    SmemGemm* sm = (SmemGemm*)dynsm;
    __shared__ const float* rp1[64];
    const int t = blockIdx.y;
    if (threadIdx.x < 64) {
        int tok = input[threadIdx.x * TT + t];
        rp1[threadIdx.x] = word_lut + (size_t)tok * EE;
    }
    __syncthreads();
    gemm_async(blockIdx.x * 256, 0, EE, g_WfE, EE / 16,
               rp1, rp1, 1 << 30, g_pre + (size_t)t * 4096 * 64, sm, 0, 0);
}

// ---------------- step phases ----------------
__device__ __forceinline__ void cell_phase(int layer, int t) {
    int e = blockIdx.x * NTHR + threadIdx.x;    // 65536 = BB*DD
    int b = e & 63, d = e >> 6;
    const float* bias = layer ? g_bias1 : g_bias0;
    float gg[4];
    #pragma unroll
    for (int gate = 0; gate < 4; gate++) {
        int row = gate * DD + d;
        float s = bias[row];
        if (layer == 0) s += g_pre[((size_t)t * 4096 + row) * 64 + b];
        #pragma unroll
        for (int ks = 0; ks < 8; ks++)
            s += g_part[((size_t)ks * 4096 + row) * 64 + b];
        gg[gate] = s;
    }
    if (layer) {
        float cn = sigm(gg[1]) * g_c1[b][d] + sigm(gg[0]) * tanhf(gg[2]);
        g_c1[b][d] = cn;
        g_h1[b][d] = sigm(gg[3]) * tanhf(cn);
    } else {
        float cn = sigm(gg[1]) * g_c0[b][d] + sigm(gg[0]) * tanhf(gg[2]);
        g_c0[b][d] = cn;
        g_h0[b][d] = sigm(gg[3]) * tanhf(cn);
    }
}

__device__ __forceinline__ void attn_phase(
    int t, float* __restrict__ attns,
    SmemAttn* sm, float* sc, float* red) {
    const int tid = threadIdx.x;
    const int b = blockIdx.x >> 1;
    const int half = blockIdx.x & 1;
    const int lane = tid & 31, warp = tid >> 5;

    for (int i = tid; i < DD; i += NTHR) sm->h1s[i] = g_h1[b][i];
    __syncthreads();

    // scores[s] = Cq16[s,b,:] . h1
    #pragma unroll
    for (int i = 0; i < 8; i++) {
        int s = warp + 16 * i;
        const uint4* cp = (const uint4*)(g_Cq16 + (size_t)(s * BB + b) * DD);
        float p = 0.f;
        #pragma unroll
        for (int jj = 0; jj < 4; jj++) {
            int u = lane + jj * 32;
            uint4 q = cp[u];
            const __half2* hh = (const __half2*)&q;
            float2 f0 = __half22float2(hh[0]);
            float2 f1 = __half22float2(hh[1]);
            float2 f2 = __half22float2(hh[2]);
            float2 f3 = __half22float2(hh[3]);
            int base = u * 8;
            p += f0.x * sm->h1s[base]     + f0.y * sm->h1s[base + 1] +
                 f1.x * sm->h1s[base + 2] + f1.y * sm->h1s[base + 3] +
                 f2.x * sm->h1s[base + 4] + f2.y * sm->h1s[base + 5] +
                 f3.x * sm->h1s[base + 6] + f3.y * sm->h1s[base + 7];
        }
        #pragma unroll
        for (int off = 16; off; off >>= 1) p += __shfl_xor_sync(~0u, p, off);
        if (lane == 0) sc[s] = p;
    }
    __syncthreads();

    float v = (tid < 128) ? sc[tid] : -1e30f;
    float m = v;
    #pragma unroll
    for (int off = 16; off; off >>= 1) m = fmaxf(m, __shfl_xor_sync(~0u, m, off));
    if (tid < 128 && lane == 0) red[warp] = m;
    __syncthreads();
    m = fmaxf(fmaxf(red[0], red[1]), fmaxf(red[2], red[3]));
    float ex = (tid < 128) ? __expf(v - m) : 0.f;
    float ssum = ex;
    #pragma unroll
    for (int off = 16; off; off >>= 1) ssum += __shfl_xor_sync(~0u, ssum, off);
    if (tid < 128 && lane == 0) red[4 + warp] = ssum;
    __syncthreads();
    ssum = red[4] + red[5] + red[6] + red[7];
    if (tid < 128) {
        float a = ex / ssum;
        sc[tid] = a;
        if (half == 0) attns[((size_t)b * TT + t) * SS + tid] = a;
    }
    __syncthreads();

    // wctx[d] = sum_s a[s] * ctx16[s,b,d]; 8 s-groups x 64 d8-columns
    const int g8 = tid >> 6, j = tid & 63;
    const int d8 = half * 512 + j * 8;
    float a8[8];
    #pragma unroll
    for (int q = 0; q < 8; q++) a8[q] = 0.f;
    for (int s = g8 * 16; s < g8 * 16 + 16; s++) {
        float as = sc[s];
        uint4 vv = *(const uint4*)(g_ctx16 + (size_t)(s * BB + b) * DD + d8);
        const __half2* hh = (const __half2*)&vv;
        float2 f0 = __half22float2(hh[0]);
        float2 f1 = __half22float2(hh[1]);
        float2 f2 = __half22float2(hh[2]);
        float2 f3 = __half22float2(hh[3]);
        a8[0] += as * f0.x; a8[1] += as * f0.y;
        a8[2] += as * f1.x; a8[3] += as * f1.y;
        a8[4] += as * f2.x; a8[5] += as * f2.y;
        a8[6] += as * f3.x; a8[7] += as * f3.y;
    }
    #pragma unroll
    for (int q = 0; q < 8; q++) sm->wbuf[g8][j][q] = a8[q];
    __syncthreads();
    if (g8 == 0) {
        float o[8];
        #pragma unroll
        for (int q = 0; q < 8; q++) o[q] = 0.f;
        #pragma unroll
        for (int gg = 0; gg < 8; gg++)
            #pragma unroll
            for (int q = 0; q < 8; q++) o[q] += sm->wbuf[gg][j][q];
        *(float4*)&g_wctx[b][d8]     = make_float4(o[0], o[1], o[2], o[3]);
        *(float4*)&g_wctx[b][d8 + 4] = make_float4(o[4], o[5], o[6], o[7]);
    }
    __syncthreads();
}

__device__ __forceinline__ void outred_phase(int t, float* __restrict__ outs) {
    int e = blockIdx.x * NTHR + threadIdx.x;
    int b = e & 63, d = e >> 6;
    float s = 0.f;
    #pragma unroll
    for (int ks = 0; ks < 32; ks++)
        s += g_part[((size_t)ks * 1024 + d) * 64 + b];
    float v = tanhf(s);
    g_out[b][d] = v;
    outs[((size_t)b * TT + t) * DD + d] = v;
}

// ---------------- persistent kernel: all 128 timesteps ----------------
__global__ __launch_bounds__(NTHR, 1) void main_kernel(
    float* __restrict__ outs, float* __restrict__ attns) {
    extern __shared__ char dynsm[];
    SmemU* sm = (SmemU*)dynsm;
    __shared__ const float* rp1[64];
    __shared__ const float* rp2[64];
    __shared__ float sc[SS];
    __shared__ float red[8];
    const int tid = threadIdx.x;
    const int bid = blockIdx.x;

    for (int t = 0; t < TT; t++) {
        // lstm0 gates: x = [out | h0], K=2048, 16 rowtiles x 8 ksplit
        if (tid < 64) { rp1[tid] = &g_out[tid][0]; rp2[tid] = &g_h0[tid][0]; }
        __syncthreads();
        gemm_async((bid & 15) * 256, (bid >> 4) * 256, 256, g_Wf0, 128,
                   rp1, rp2, DD, g_part + (size_t)(bid >> 4) * 4096 * 64, &sm->g, 0, 0);
        grid_barrier();
        cell_phase(0, t);
        grid_barrier();
        // lstm1 gates: x = [h0 | h1]
        if (tid < 64) { rp1[tid] = &g_h0[tid][0]; rp2[tid] = &g_h1[tid][0]; }
        __syncthreads();
        gemm_async((bid & 15) * 256, (bid >> 4) * 256, 256, g_Wf1, 128,
                   rp1, rp2, DD, g_part + (size_t)(bid >> 4) * 4096 * 64, &sm->g, 0, 0);
        grid_barrier();
        cell_phase(1, t);
        grid_barrier();
        attn_phase(t, attns, &sm->a, sc, red);
        grid_barrier();
        // out gemm: x = [wctx | h1], 4 rowtiles x 32 ksplit
        if (tid < 64) { rp1[tid] = &g_wctx[tid][0]; rp2[tid] = &g_h1[tid][0]; }
        __syncthreads();
        gemm_async((bid & 3) * 256, (bid >> 2) * 64, 64, g_WfO, 128,
                   rp1, rp2, DD, g_part + (size_t)(bid >> 2) * 1024 * 64, &sm->g, 0, 0);
        grid_barrier();
        outred_phase(t, outs);
        grid_barrier();     // next step's lstm0 reads g_out
    }
}

// ---------------- final ----------------
__global__ void final_kernel(float* __restrict__ hout, float* __restrict__ cout) {
    int i = blockIdx.x * blockDim.x + threadIdx.x;
    if (i < BB * DD) {
        hout[i]           = ((float*)g_h0)[i];
        hout[BB * DD + i] = ((float*)g_h1)[i];
        cout[i]           = ((float*)g_c0)[i];
        cout[BB * DD + i] = ((float*)g_c1)[i];
    }
}

// ---------------- launch ----------------
extern "C" void kernel_launch(void* const* d_in, const int* in_sizes, int n_in,
                              void* d_out, int out_size) {
    const int*   input    = (const int*)d_in[0];
    const float* h0       = (const float*)d_in[2];
    const float* c0       = (const float*)d_in[3];
    const float* context  = (const float*)d_in[4];
    const float* init_out = (const float*)d_in[5];
    const float* word_lut = (const float*)d_in[6];
    const float* Wih0 = (const float*)d_in[7];
    const float* Whh0 = (const float*)d_in[8];
    const float* bih0 = (const float*)d_in[9];
    const float* bhh0 = (const float*)d_in[10];
    const float* Wih1 = (const float*)d_in[11];
    const float* Whh1 = (const float*)d_in[12];
    const float* bih1 = (const float*)d_in[13];
    const float* bhh1 = (const float*)d_in[14];
    const float* Win  = (const float*)d_in[15];
    const float* Wout = (const float*)d_in[16];

    float* out   = (float*)d_out;
    float* outs  = out;                           // [B,T,D]
    float* hout  = out + (size_t)BB * TT * DD;    // [2,B,D]
    float* cout  = hout + 2 * BB * DD;            // [2,B,D]
    float* attns = cout + 2 * BB * DD;            // [B,T,S]

    cudaFuncSetAttribute(main_kernel, cudaFuncAttributeMaxDynamicSharedMemorySize,
                         (int)sizeof(SmemU));
    cudaFuncSetAttribute(pre_emb_kernel, cudaFuncAttributeMaxDynamicSharedMemorySize,
                         (int)sizeof(SmemGemm));
    cudaFuncSetAttribute(cq16_kernel, cudaFuncAttributeMaxDynamicSharedMemorySize,
                         (int)sizeof(SmemGemm));

    init_kernel<<<256, 256>>>(h0, c0, init_out, bih0, bhh0, bih1, bhh1);
    ctx16_kernel<<<32768, 256>>>(context);
    // packs: (W1, ld1, off1, W2, ld2, K1w, K16tot, mbTot, which, trans)
    pack_kernel<<<1024, 256>>>(Wih0, 1536, 0,   Wih0, 1536, 512,  32,  256, 0, 0);
    pack_kernel<<<4096, 256>>>(Wih0, 1536, 512, Whh0, 1024, 1024, 128, 256, 1, 0);
    pack_kernel<<<4096, 256>>>(Wih1, 1024, 0,   Whh1, 1024, 1024, 128, 256, 2, 0);
    pack_kernel<<<1024, 256>>>(Wout, 2048, 0,   Wout, 2048, 2048, 128, 64,  3, 0);
    pack_kernel<<<512, 256>>>(Win,  1024, 0,   Win,  1024, 1024, 64,  64,  4, 1);
    cq16_kernel<<<dim3(4, 128), NTHR, sizeof(SmemGemm)>>>(context);
    pre_emb_kernel<<<dim3(16, 128), NTHR, sizeof(SmemGemm)>>>(input, word_lut);
    main_kernel<<<NCTA, NTHR, sizeof(SmemU)>>>(outs, attns);
    final_kernel<<<256, 256>>>(hout, cout);
}